// round 12
// baseline (speedup 1.0000x reference)
#include <cuda_runtime.h>
#include <cuda_bf16.h>
#include <cstdint>
#include <stdint.h>
#include <math.h>

// Problem constants (fixed by the dataset)
#define BB 4
#define NN 2048
#define CC 1024
#define HH 16
#define HD 64
#define LR 20
#define RR 200
#define M_TOK (BB * NN)   // 8192 token rows

// ---------------- scratch (__device__ globals; no allocs allowed) -----------
__device__ __nv_bfloat16 g_xh[(size_t)M_TOK * CC];
__device__ __nv_bfloat16 g_xl[(size_t)M_TOK * CC];
__device__ __nv_bfloat16 g_qkwh[(size_t)2 * CC * CC];
__device__ __nv_bfloat16 g_qkwl[(size_t)2 * CC * CC];
__device__ __nv_bfloat16 g_pwh[(size_t)CC * CC];
__device__ __nv_bfloat16 g_pwl[(size_t)CC * CC];
__device__ __nv_bfloat16 g_ah[(size_t)M_TOK * CC];   // attn hi (split at source)
__device__ __nv_bfloat16 g_al[(size_t)M_TOK * CC];   // attn lo

// normalized q|k per head, [bh][n][128] (0-63 = q, 64-127 = k), bf16 hi/lo
__device__ __nv_bfloat16 g_qnh[(size_t)BB * HH * NN * 128];
__device__ __nv_bfloat16 g_qnl[(size_t)BB * HH * NN * 128];
// combined per-(b,h) weights [bh][o(64)][d(128)]
__device__ __nv_bfloat16 g_bwh[(size_t)BB * HH * HD * 128];
__device__ __nv_bfloat16 g_bwl[(size_t)BB * HH * HD * 128];

// ---------------- helpers ----------------------------------------------------
__device__ __forceinline__ uint32_t smem_u32(const void* p) {
    uint32_t a;
    asm("{ .reg .u64 t; cvta.to.shared.u64 t, %1; cvt.u32.u64 %0, t; }" : "=r"(a) : "l"(p));
    return a;
}
__device__ __forceinline__ void ldm_x4(uint32_t* r, uint32_t addr) {
    asm volatile("ldmatrix.sync.aligned.m8n8.x4.shared.b16 {%0,%1,%2,%3}, [%4];"
        : "=r"(r[0]), "=r"(r[1]), "=r"(r[2]), "=r"(r[3]) : "r"(addr));
}
__device__ __forceinline__ void mma_bf16(float* c, const uint32_t* a, const uint32_t* b) {
    asm volatile("mma.sync.aligned.m16n8k16.row.col.f32.bf16.bf16.f32 "
        "{%0,%1,%2,%3}, {%4,%5,%6,%7}, {%8,%9}, {%0,%1,%2,%3};"
        : "+f"(c[0]), "+f"(c[1]), "+f"(c[2]), "+f"(c[3])
        : "r"(a[0]), "r"(a[1]), "r"(a[2]), "r"(a[3]), "r"(b[0]), "r"(b[1]));
}
__device__ __forceinline__ void cpasync16(uint32_t dst, const void* src) {
    asm volatile("cp.async.cg.shared.global [%0], [%1], 16;" :: "r"(dst), "l"(src));
}
__device__ __forceinline__ void split_store2(float a, float b,
                                             __nv_bfloat16* hp, __nv_bfloat16* lp) {
    __nv_bfloat16 h0 = __float2bfloat16(a);
    __nv_bfloat16 h1 = __float2bfloat16(b);
    *(__nv_bfloat162*)hp = __nv_bfloat162(h0, h1);
    *(__nv_bfloat162*)lp = __nv_bfloat162(
        __float2bfloat16(a - __bfloat162float(h0)),
        __float2bfloat16(b - __bfloat162float(h1)));
}

// ---------------------------------------------------------------------------
// merged split: x, qk_w, proj_w -> bf16 hi/lo, one launch.
// ---------------------------------------------------------------------------
#define N4_X   (M_TOK * CC / 4)       // 2,097,152
#define N4_QKW (2 * CC * CC / 4)      //   524,288
#define N4_PW  (CC * CC / 4)          //   262,144
#define N4_TOT (N4_X + N4_QKW + N4_PW)

__global__ __launch_bounds__(256) void split3_kernel(
    const float* __restrict__ x, const float* __restrict__ qkw,
    const float* __restrict__ pw)
{
    int i = blockIdx.x * 256 + threadIdx.x;
    const float* src; __nv_bfloat16 *hi, *lo;
    if (i < N4_X)                { src = x;   hi = g_xh;   lo = g_xl; }
    else if (i < N4_X + N4_QKW)  { i -= N4_X; src = qkw; hi = g_qkwh; lo = g_qkwl; }
    else if (i < N4_TOT)         { i -= N4_X + N4_QKW; src = pw; hi = g_pwh; lo = g_pwl; }
    else return;

    float4 v = ((const float4*)src)[i];
    __nv_bfloat16 h0 = __float2bfloat16(v.x);
    __nv_bfloat16 h1 = __float2bfloat16(v.y);
    __nv_bfloat16 h2 = __float2bfloat16(v.z);
    __nv_bfloat16 h3 = __float2bfloat16(v.w);
    __nv_bfloat162* hp = (__nv_bfloat162*)hi;
    __nv_bfloat162* lp = (__nv_bfloat162*)lo;
    hp[2 * i]     = __nv_bfloat162(h0, h1);
    hp[2 * i + 1] = __nv_bfloat162(h2, h3);
    lp[2 * i]     = __nv_bfloat162(__float2bfloat16(v.x - __bfloat162float(h0)),
                                   __float2bfloat16(v.y - __bfloat162float(h1)));
    lp[2 * i + 1] = __nv_bfloat162(__float2bfloat16(v.z - __bfloat162float(h2)),
                                   __float2bfloat16(v.w - __bfloat162float(h3)));
}

// ---------------------------------------------------------------------------
// Persistent HMMA GEMM, bf16 3-term split, cp.async double buffering.
//   MODE 1: C = A@B^T + bias (fp32 out)               [GEMM2]
//   MODE 2: fused L2-norm epilogue -> g_qnh/g_qnl     [GEMM1, N=2048]
// 128x128 tile, 8 warps (2x4), warp 64x32, BK=32, 2 CTAs/SM.
// ---------------------------------------------------------------------------
#define LDT 40
#define TILE_ELE (128 * LDT)
#define TILE_BYT (TILE_ELE * 2)
#define STAGE_BYT (4 * TILE_BYT)
#define GEMM_SMEM (2 * STAGE_BYT)    // 81920 bytes

template <int MODE>
__global__ __launch_bounds__(256, 2) void gemm3h_kernel(
    const __nv_bfloat16* __restrict__ Ah, const __nv_bfloat16* __restrict__ Al,
    const __nv_bfloat16* __restrict__ Bh, const __nv_bfloat16* __restrict__ Bl,
    const float* __restrict__ bias, float* __restrict__ C,
    int ntiles, int nx, int Nc, int K)
{
    extern __shared__ __nv_bfloat16 smem[];
    const int t = threadIdx.x;
    const int lane = t & 31, wid = t >> 5;
    const int warpM = wid & 1;
    const int warpN = wid >> 1;
    const uint32_t smb = smem_u32(smem);

    const int lr0 = t >> 2;             // 0..63
    const int lc4 = t & 3;              // 16B chunk

    const int a_row = warpM * 64 + (lane & 15);
    const int a_colh = (lane >> 4) << 3;
    const int b_row = warpN * 32 + ((lane >> 4) << 3) + (lane & 7);
    const int b_colh = ((lane >> 3) & 1) << 3;
    const int g = lane >> 2;
    const int cp = (lane & 3) * 2;

    const int NIT = K / 32;

    for (int tile = blockIdx.x; tile < ntiles; tile += gridDim.x) {
        const int mbase = (tile / nx) * 128;
        const int nbase = (tile % nx) * 128;
        const __nv_bfloat16* base[4] = {
            Ah + (size_t)mbase * K, Al + (size_t)mbase * K,
            Bh + (size_t)nbase * K, Bl + (size_t)nbase * K };

        float acc[4][4][4];
#pragma unroll
        for (int m = 0; m < 4; m++)
#pragma unroll
            for (int n = 0; n < 4; n++)
#pragma unroll
                for (int j = 0; j < 4; j++) acc[m][n][j] = 0.f;

        // prologue: stage 0
        {
            uint32_t sb = smb;
#pragma unroll
            for (int tl = 0; tl < 4; tl++) {
                const __nv_bfloat16* gp = base[tl] + (size_t)lr0 * K + lc4 * 8;
                uint32_t dp = sb + tl * TILE_BYT + (lr0 * LDT + lc4 * 8) * 2;
                cpasync16(dp, gp);
                cpasync16(dp + 64 * LDT * 2, gp + (size_t)64 * K);
            }
            asm volatile("cp.async.commit_group;");
        }

        for (int it = 0; it < NIT; it++) {
            int cur = it & 1;
            if (it + 1 < NIT) {
                uint32_t sb = smb + (cur ^ 1) * STAGE_BYT;
                int kt = (it + 1) * 32;
#pragma unroll
                for (int tl = 0; tl < 4; tl++) {
                    const __nv_bfloat16* gp = base[tl] + (size_t)lr0 * K + kt + lc4 * 8;
                    uint32_t dp = sb + tl * TILE_BYT + (lr0 * LDT + lc4 * 8) * 2;
                    cpasync16(dp, gp);
                    cpasync16(dp + 64 * LDT * 2, gp + (size_t)64 * K);
                }
                asm volatile("cp.async.commit_group;");
                asm volatile("cp.async.wait_group 1;");
            } else {
                asm volatile("cp.async.wait_group 0;");
            }
            __syncthreads();

            uint32_t sa = smb + cur * STAGE_BYT;
#pragma unroll
            for (int kk = 0; kk < 32; kk += 16) {
                uint32_t ahf[4][4], alf[4][4];
#pragma unroll
                for (int m = 0; m < 4; m++) {
                    uint32_t off = ((a_row + m * 16) * LDT + kk + a_colh) * 2;
                    ldm_x4(ahf[m], sa + off);
                    ldm_x4(alf[m], sa + TILE_BYT + off);
                }
                uint32_t bhf[2][4], blf[2][4];
#pragma unroll
                for (int p = 0; p < 2; p++) {
                    uint32_t off = ((b_row + p * 16) * LDT + kk + b_colh) * 2;
                    ldm_x4(bhf[p], sa + 2 * TILE_BYT + off);
                    ldm_x4(blf[p], sa + 3 * TILE_BYT + off);
                }
#pragma unroll
                for (int m = 0; m < 4; m++) {
#pragma unroll
                    for (int n = 0; n < 4; n++) {
                        const uint32_t* b2h = &bhf[n >> 1][(n & 1) * 2];
                        const uint32_t* b2l = &blf[n >> 1][(n & 1) * 2];
                        mma_bf16(acc[m][n], ahf[m], b2h);
                        mma_bf16(acc[m][n], ahf[m], b2l);
                        mma_bf16(acc[m][n], alf[m], b2h);
                    }
                }
            }
            if (it + 1 < NIT) __syncthreads();
        }

        __syncthreads();   // all compute done; smem reusable

        if (MODE == 1) {
            // plain fp32 + bias epilogue
#pragma unroll
            for (int m = 0; m < 4; m++) {
                int row0 = mbase + warpM * 64 + m * 16 + g;
#pragma unroll
                for (int n = 0; n < 4; n++) {
                    int col = nbase + warpN * 32 + n * 8 + cp;
                    float b0 = bias[col], b1 = bias[col + 1];
                    *(float2*)(C + (size_t)row0 * Nc + col) =
                        make_float2(acc[m][n][0] + b0, acc[m][n][1] + b1);
                    *(float2*)(C + (size_t)(row0 + 8) * Nc + col) =
                        make_float2(acc[m][n][2] + b0, acc[m][n][3] + b1);
                }
            }
        } else {
            // fused L2 norm over 64-col head groups, emit bf16 hi/lo per-head.
            float* sred = (float*)smem;          // [128 rows][4 warpN]
#pragma unroll
            for (int m = 0; m < 4; m++) {
                float p0 = 0.f, p1 = 0.f;
#pragma unroll
                for (int n = 0; n < 4; n++) {
                    p0 += acc[m][n][0] * acc[m][n][0] + acc[m][n][1] * acc[m][n][1];
                    p1 += acc[m][n][2] * acc[m][n][2] + acc[m][n][3] * acc[m][n][3];
                }
                p0 += __shfl_xor_sync(0xffffffffu, p0, 1);
                p0 += __shfl_xor_sync(0xffffffffu, p0, 2);
                p1 += __shfl_xor_sync(0xffffffffu, p1, 1);
                p1 += __shfl_xor_sync(0xffffffffu, p1, 2);
                if ((lane & 3) == 0) {
                    sred[(warpM * 64 + m * 16 + g) * 4 + warpN] = p0;
                    sred[(warpM * 64 + m * 16 + g + 8) * 4 + warpN] = p1;
                }
            }
            __syncthreads();
#pragma unroll
            for (int m = 0; m < 4; m++) {
#pragma unroll
                for (int half = 0; half < 2; half++) {
                    int rloc = warpM * 64 + m * 16 + g + half * 8;
                    float s = sred[rloc * 4 + warpN] + sred[rloc * 4 + (warpN ^ 1)];
                    float inv = 1.0f / fmaxf(sqrtf(s), 1e-12f);
                    int rowg = mbase + rloc;
                    int b = rowg >> 11, ntok = rowg & 2047;
#pragma unroll
                    for (int n = 0; n < 4; n++) {
                        int col = nbase + warpN * 32 + n * 8 + cp;
                        int isk = col >> 10;
                        int cc = col & 1023;
                        int h = cc >> 6, d = (cc & 63) + isk * 64;
                        size_t off = (((size_t)(b * HH + h)) * NN + ntok) * 128 + d;
                        split_store2(acc[m][n][half * 2] * inv,
                                     acc[m][n][half * 2 + 1] * inv,
                                     g_qnh + off, g_qnl + off);
                    }
                }
            }
            __syncthreads();   // sred reads done before next tile's cp.async
        }
    }
}

// ---------------------------------------------------------------------------
// genw: per (b,h) fold subsampled low-rank weights with cw_w -> BW bf16 hi/lo
// ---------------------------------------------------------------------------
__global__ __launch_bounds__(256) void genw_kernel(
    const float* __restrict__ x, const float* __restrict__ we,
    const float* __restrict__ wr, const float* __restrict__ cw_w)
{
    int bh = blockIdx.x;
    int b = bh >> 4, h = bh & 15;
    __shared__ int   idx_s[RR];
    __shared__ float web[HD][LR], wrb[HD][LR];
    int t = threadIdx.x;

    if (t < RR) idx_s[t] = (int)((double)t * (double)(NN - 1) / (double)(RR - 1));
    __syncthreads();

    for (int it = t; it < HD * LR; it += 256) {
        int d = it / LR, e = it % LR;
        float se = 0.f, sr = 0.f;
        for (int r = 0; r < RR; r++) {
            float xv = x[((size_t)b * NN + idx_s[r]) * CC + h * HD + d];
            se += xv * we[((size_t)h * RR + r) * LR + e];
            sr += xv * wr[((size_t)h * RR + r) * LR + e];
        }
        web[d][e] = se;
        wrb[d][e] = sr;
    }
    __syncthreads();

    __nv_bfloat16* bwh = g_bwh + (size_t)bh * HD * 128;
    __nv_bfloat16* bwl = g_bwl + (size_t)bh * HD * 128;
    for (int it = t; it < HD * HD; it += 256) {
        int d = it >> 6, o = it & 63;
        float ae = 0.f, ar = 0.f;
#pragma unroll
        for (int e = 0; e < LR; e++) {
            ae += web[d][e] * cw_w[o * (2 * LR) + e];
            ar += wrb[d][e] * cw_w[o * (2 * LR) + LR + e];
        }
        __nv_bfloat16 ha = __float2bfloat16(ae);
        __nv_bfloat16 hr = __float2bfloat16(ar);
        bwh[o * 128 + d]      = ha;
        bwh[o * 128 + 64 + d] = hr;
        bwl[o * 128 + d]      = __float2bfloat16(ae - __bfloat162float(ha));
        bwl[o * 128 + 64 + d] = __float2bfloat16(ar - __bfloat162float(hr));
    }
}

// ---------------------------------------------------------------------------
// score via HMMA: per bh, attn_tile[256,64] = QK[256,128] @ BW[64,128]^T + cw_b
// 3-term bf16 split; output written directly as bf16 hi/lo (feeds GEMM2).
// ---------------------------------------------------------------------------
#define SC_SMEM ((2 * 256 * LDT + 2 * 64 * LDT) * 2)

__global__ __launch_bounds__(256, 2) void score_mma_kernel(const float* __restrict__ cw_b)
{
    extern __shared__ __nv_bfloat16 ssm[];
    __nv_bfloat16* sAh = ssm;                      // 256*40
    __nv_bfloat16* sAl = ssm + 256 * LDT;
    __nv_bfloat16* sBh = ssm + 2 * 256 * LDT;      // 64*40
    __nv_bfloat16* sBl = ssm + 2 * 256 * LDT + 64 * LDT;

    const int t = threadIdx.x;
    const int lane = t & 31, wid = t >> 5;
    const int warpM = wid >> 1;
    const int warpN = wid & 1;
    const int tileM = blockIdx.x;      // 0..7 (256-token tiles)
    const int bh = blockIdx.y;
    const int b = bh >> 4, h = bh & 15;

    const __nv_bfloat16* Abh = g_qnh + ((size_t)bh * NN + tileM * 256) * 128;
    const __nv_bfloat16* Abl = g_qnl + ((size_t)bh * NN + tileM * 256) * 128;
    const __nv_bfloat16* Bbh = g_bwh + (size_t)bh * HD * 128;
    const __nv_bfloat16* Bbl = g_bwl + (size_t)bh * HD * 128;

    const uint32_t smb = smem_u32(ssm);
    const uint32_t offAl = 256 * LDT * 2;
    const uint32_t offBh = 2 * 256 * LDT * 2;
    const uint32_t offBl = offBh + 64 * LDT * 2;

    float acc[4][4][4];
#pragma unroll
    for (int m = 0; m < 4; m++)
#pragma unroll
        for (int n = 0; n < 4; n++)
#pragma unroll
            for (int j = 0; j < 4; j++) acc[m][n][j] = 0.f;

    const int a_row = warpM * 64 + (lane & 15);
    const int a_colh = (lane >> 4) << 3;
    const int b_row = warpN * 32 + ((lane >> 4) << 3) + (lane & 7);
    const int b_colh = ((lane >> 3) & 1) << 3;

    for (int ck = 0; ck < 4; ck++) {
        int kt = ck * 32;
        if (ck) __syncthreads();
#pragma unroll
        for (int j = 0; j < 4; j++) {
            int idx = t + j * 256;
            int row = idx >> 2, c = idx & 3;
            *(uint4*)(sAh + row * LDT + c * 8) = *(const uint4*)(Abh + (size_t)row * 128 + kt + c * 8);
            *(uint4*)(sAl + row * LDT + c * 8) = *(const uint4*)(Abl + (size_t)row * 128 + kt + c * 8);
        }
        {
            int row = t >> 2, c = t & 3;
            if (row < 64) {
                *(uint4*)(sBh + row * LDT + c * 8) = *(const uint4*)(Bbh + (size_t)row * 128 + kt + c * 8);
                *(uint4*)(sBl + row * LDT + c * 8) = *(const uint4*)(Bbl + (size_t)row * 128 + kt + c * 8);
            }
        }
        __syncthreads();

#pragma unroll
        for (int kk = 0; kk < 32; kk += 16) {
            uint32_t ahf[4][4], alf[4][4];
#pragma unroll
            for (int m = 0; m < 4; m++) {
                uint32_t off = ((a_row + m * 16) * LDT + kk + a_colh) * 2;
                ldm_x4(ahf[m], smb + off);
                ldm_x4(alf[m], smb + offAl + off);
            }
            uint32_t bhf[2][4], blf[2][4];
#pragma unroll
            for (int p = 0; p < 2; p++) {
                uint32_t off = ((b_row + p * 16) * LDT + kk + b_colh) * 2;
                ldm_x4(bhf[p], smb + offBh + off);
                ldm_x4(blf[p], smb + offBl + off);
            }
#pragma unroll
            for (int m = 0; m < 4; m++) {
#pragma unroll
                for (int n = 0; n < 4; n++) {
                    const uint32_t* b2h = &bhf[n >> 1][(n & 1) * 2];
                    const uint32_t* b2l = &blf[n >> 1][(n & 1) * 2];
                    mma_bf16(acc[m][n], ahf[m], b2h);
                    mma_bf16(acc[m][n], ahf[m], b2l);
                    mma_bf16(acc[m][n], alf[m], b2h);
                }
            }
        }
    }

    const int g = lane >> 2;
    const int cp = (lane & 3) * 2;
#pragma unroll
    for (int m = 0; m < 4; m++) {
        int n_tok = tileM * 256 + warpM * 64 + m * 16 + g;
#pragma unroll
        for (int n = 0; n < 4; n++) {
            int col = warpN * 32 + n * 8 + cp;
            float b0 = cw_b[col], b1 = cw_b[col + 1];
            size_t r0 = ((size_t)(b * NN + n_tok)) * CC + h * HD + col;
            size_t r1 = ((size_t)(b * NN + n_tok + 8)) * CC + h * HD + col;
            split_store2(acc[m][n][0] + b0, acc[m][n][1] + b1, g_ah + r0, g_al + r0);
            split_store2(acc[m][n][2] + b0, acc[m][n][3] + b1, g_ah + r1, g_al + r1);
        }
    }
}

// ---------------------------------------------------------------------------
extern "C" void kernel_launch(void* const* d_in, const int* in_sizes, int n_in,
                              void* d_out, int out_size)
{
    const float* x      = (const float*)d_in[0];
    const float* qk_w   = (const float*)d_in[1];
    const float* proj_w = (const float*)d_in[2];
    const float* proj_b = (const float*)d_in[3];
    const float* we     = (const float*)d_in[4];
    const float* wr     = (const float*)d_in[5];
    const float* cw_w   = (const float*)d_in[6];
    const float* cw_b   = (const float*)d_in[7];
    float* out = (float*)d_out;

    void *p_xh, *p_xl, *p_qkwh, *p_qkwl, *p_pwh, *p_pwl, *p_ah, *p_al;
    cudaGetSymbolAddress(&p_xh, g_xh);
    cudaGetSymbolAddress(&p_xl, g_xl);
    cudaGetSymbolAddress(&p_qkwh, g_qkwh);
    cudaGetSymbolAddress(&p_qkwl, g_qkwl);
    cudaGetSymbolAddress(&p_pwh, g_pwh);
    cudaGetSymbolAddress(&p_pwl, g_pwl);
    cudaGetSymbolAddress(&p_ah, g_ah);
    cudaGetSymbolAddress(&p_al, g_al);

    cudaFuncSetAttribute(gemm3h_kernel<1>, cudaFuncAttributeMaxDynamicSharedMemorySize, GEMM_SMEM);
    cudaFuncSetAttribute(gemm3h_kernel<2>, cudaFuncAttributeMaxDynamicSharedMemorySize, GEMM_SMEM);
    cudaFuncSetAttribute(score_mma_kernel, cudaFuncAttributeMaxDynamicSharedMemorySize, SC_SMEM);

    const int PGRID = 304;   // 2 CTAs/SM x 152 SMs

    // 0) split x, qk_w, proj_w to bf16 hi/lo (one launch)
    split3_kernel<<<(N4_TOT + 255) / 256, 256>>>(x, qk_w, proj_w);

    // 1) GEMM1 + fused l2norm: writes g_qnh/g_qnl directly (persistent)
    gemm3h_kernel<2><<<PGRID, 256, GEMM_SMEM>>>(
        (const __nv_bfloat16*)p_xh, (const __nv_bfloat16*)p_xl,
        (const __nv_bfloat16*)p_qkwh, (const __nv_bfloat16*)p_qkwl,
        nullptr, nullptr, (M_TOK / 128) * (2 * CC / 128), 2 * CC / 128, 2 * CC, CC);

    // 2) fold low-rank weights -> BW bf16 hi/lo
    genw_kernel<<<BB * HH, 256>>>(x, we, wr, cw_w);

    // 3) attn = [q|k] @ BW^T + cw_b  (HMMA), output split bf16 hi/lo
    score_mma_kernel<<<dim3(NN / 256, BB * HH), 256, SC_SMEM>>>(cw_b);

    // 4) out = attn @ proj_w^T + proj_b  (persistent)
    gemm3h_kernel<1><<<PGRID, 256, GEMM_SMEM>>>(
        (const __nv_bfloat16*)p_ah, (const __nv_bfloat16*)p_al,
        (const __nv_bfloat16*)p_pwh, (const __nv_bfloat16*)p_pwl,
        proj_b, out, (M_TOK / 128) * (CC / 128), CC / 128, CC, CC);
}

// round 14
// speedup vs baseline: 1.0843x; 1.0843x over previous
#include <cuda_runtime.h>
#include <cuda_bf16.h>
#include <cstdint>
#include <stdint.h>
#include <math.h>

// Problem constants (fixed by the dataset)
#define BB 4
#define NN 2048
#define CC 1024
#define HH 16
#define HD 64
#define LR 20
#define RR 200
#define M_TOK (BB * NN)   // 8192 token rows

// ---------------- scratch (__device__ globals; no allocs allowed) -----------
__device__ float g_qk[(size_t)M_TOK * 2 * CC];   // [8192][2048] q|k fp32

__device__ __nv_bfloat16 g_xh[(size_t)M_TOK * CC];
__device__ __nv_bfloat16 g_xl[(size_t)M_TOK * CC];
__device__ __nv_bfloat16 g_qkwh[(size_t)2 * CC * CC];
__device__ __nv_bfloat16 g_qkwl[(size_t)2 * CC * CC];
__device__ __nv_bfloat16 g_pwh[(size_t)CC * CC];
__device__ __nv_bfloat16 g_pwl[(size_t)CC * CC];
__device__ __nv_bfloat16 g_ah[(size_t)M_TOK * CC];   // attn hi (split at source)
__device__ __nv_bfloat16 g_al[(size_t)M_TOK * CC];   // attn lo

// normalized q|k per head, [bh][n][128] (0-63 = q, 64-127 = k), bf16 hi/lo
__device__ __nv_bfloat16 g_qnh[(size_t)BB * HH * NN * 128];
__device__ __nv_bfloat16 g_qnl[(size_t)BB * HH * NN * 128];
// combined per-(b,h) weights [bh][o(64)][d(128)]
__device__ __nv_bfloat16 g_bwh[(size_t)BB * HH * HD * 128];
__device__ __nv_bfloat16 g_bwl[(size_t)BB * HH * HD * 128];

// ---------------- helpers ----------------------------------------------------
__device__ __forceinline__ uint32_t smem_u32(const void* p) {
    uint32_t a;
    asm("{ .reg .u64 t; cvta.to.shared.u64 t, %1; cvt.u32.u64 %0, t; }" : "=r"(a) : "l"(p));
    return a;
}
__device__ __forceinline__ void ldm_x4(uint32_t* r, uint32_t addr) {
    asm volatile("ldmatrix.sync.aligned.m8n8.x4.shared.b16 {%0,%1,%2,%3}, [%4];"
        : "=r"(r[0]), "=r"(r[1]), "=r"(r[2]), "=r"(r[3]) : "r"(addr));
}
__device__ __forceinline__ void mma_bf16(float* c, const uint32_t* a, const uint32_t* b) {
    asm volatile("mma.sync.aligned.m16n8k16.row.col.f32.bf16.bf16.f32 "
        "{%0,%1,%2,%3}, {%4,%5,%6,%7}, {%8,%9}, {%0,%1,%2,%3};"
        : "+f"(c[0]), "+f"(c[1]), "+f"(c[2]), "+f"(c[3])
        : "r"(a[0]), "r"(a[1]), "r"(a[2]), "r"(a[3]), "r"(b[0]), "r"(b[1]));
}
__device__ __forceinline__ void cpasync16(uint32_t dst, const void* src) {
    asm volatile("cp.async.cg.shared.global [%0], [%1], 16;" :: "r"(dst), "l"(src));
}
// split a float pair into bf16 hi/lo pairs and store
__device__ __forceinline__ void split_store2(float a, float b,
                                             __nv_bfloat16* hp, __nv_bfloat16* lp) {
    __nv_bfloat16 h0 = __float2bfloat16(a);
    __nv_bfloat16 h1 = __float2bfloat16(b);
    *(__nv_bfloat162*)hp = __nv_bfloat162(h0, h1);
    *(__nv_bfloat162*)lp = __nv_bfloat162(
        __float2bfloat16(a - __bfloat162float(h0)),
        __float2bfloat16(b - __bfloat162float(h1)));
}

// ---------------------------------------------------------------------------
// merged split: x, qk_w, proj_w -> bf16 hi/lo, one launch.
// ---------------------------------------------------------------------------
#define N4_X   (M_TOK * CC / 4)       // 2,097,152
#define N4_QKW (2 * CC * CC / 4)      //   524,288
#define N4_PW  (CC * CC / 4)          //   262,144
#define N4_TOT (N4_X + N4_QKW + N4_PW)

__global__ __launch_bounds__(256) void split3_kernel(
    const float* __restrict__ x, const float* __restrict__ qkw,
    const float* __restrict__ pw)
{
    int i = blockIdx.x * 256 + threadIdx.x;
    const float* src; __nv_bfloat16 *hi, *lo;
    if (i < N4_X)                { src = x;   hi = g_xh;   lo = g_xl; }
    else if (i < N4_X + N4_QKW)  { i -= N4_X; src = qkw; hi = g_qkwh; lo = g_qkwl; }
    else if (i < N4_TOT)         { i -= N4_X + N4_QKW; src = pw; hi = g_pwh; lo = g_pwl; }
    else return;

    float4 v = ((const float4*)src)[i];
    __nv_bfloat16 h0 = __float2bfloat16(v.x);
    __nv_bfloat16 h1 = __float2bfloat16(v.y);
    __nv_bfloat16 h2 = __float2bfloat16(v.z);
    __nv_bfloat16 h3 = __float2bfloat16(v.w);
    __nv_bfloat162* hp = (__nv_bfloat162*)hi;
    __nv_bfloat162* lp = (__nv_bfloat162*)lo;
    hp[2 * i]     = __nv_bfloat162(h0, h1);
    hp[2 * i + 1] = __nv_bfloat162(h2, h3);
    lp[2 * i]     = __nv_bfloat162(__float2bfloat16(v.x - __bfloat162float(h0)),
                                   __float2bfloat16(v.y - __bfloat162float(h1)));
    lp[2 * i + 1] = __nv_bfloat162(__float2bfloat16(v.z - __bfloat162float(h2)),
                                   __float2bfloat16(v.w - __bfloat162float(h3)));
}

// ---------------------------------------------------------------------------
// HMMA GEMM with bf16 3-term split + cp.async double buffering:
//   C[M,Nc] = (Ah+Al)[M,K] @ (Bh+Bl)[Nc,K]^T  (+ bias)
// 128x128 CTA tile, 8 warps (2x4), warp tile 64x32, BK=32.
// __launch_bounds__(256, 2): 2 CTAs/SM so barrier bubbles overlap across CTAs.
// ---------------------------------------------------------------------------
#define LDT 40
#define TILE_ELE (128 * LDT)
#define TILE_BYT (TILE_ELE * 2)
#define STAGE_BYT (4 * TILE_BYT)
#define GEMM_SMEM (2 * STAGE_BYT)    // 81920 bytes

template <bool BIAS>
__global__ __launch_bounds__(256, 2) void gemm3h_kernel(
    const __nv_bfloat16* __restrict__ Ah, const __nv_bfloat16* __restrict__ Al,
    const __nv_bfloat16* __restrict__ Bh, const __nv_bfloat16* __restrict__ Bl,
    const float* __restrict__ bias, float* __restrict__ C,
    int M, int Nc, int K)
{
    extern __shared__ __nv_bfloat16 smem[];
    const int t = threadIdx.x;
    const int lane = t & 31, wid = t >> 5;
    const int warpM = wid & 1;
    const int warpN = wid >> 1;
    const int mbase = blockIdx.y * 128;
    const int nbase = blockIdx.x * 128;
    const uint32_t smb = smem_u32(smem);

    const __nv_bfloat16* base[4] = {
        Ah + (size_t)mbase * K, Al + (size_t)mbase * K,
        Bh + (size_t)nbase * K, Bl + (size_t)nbase * K };

    const int lr0 = t >> 2;             // 0..63
    const int lc4 = t & 3;              // 16B chunk within 64B row

    float acc[4][4][4];
#pragma unroll
    for (int m = 0; m < 4; m++)
#pragma unroll
        for (int n = 0; n < 4; n++)
#pragma unroll
            for (int j = 0; j < 4; j++) acc[m][n][j] = 0.f;

    auto issue_stage = [&](int s, int kt) {
        uint32_t sb = smb + s * STAGE_BYT;
#pragma unroll
        for (int tl = 0; tl < 4; tl++) {
            const __nv_bfloat16* gp = base[tl] + (size_t)lr0 * K + kt + lc4 * 8;
            uint32_t dp = sb + tl * TILE_BYT + (lr0 * LDT + lc4 * 8) * 2;
            cpasync16(dp, gp);
            cpasync16(dp + 64 * LDT * 2, gp + (size_t)64 * K);
        }
        asm volatile("cp.async.commit_group;");
    };

    const int a_row = warpM * 64 + (lane & 15);
    const int a_colh = (lane >> 4) << 3;
    const int b_row = warpN * 32 + ((lane >> 4) << 3) + (lane & 7);
    const int b_colh = ((lane >> 3) & 1) << 3;

    const int NIT = K / 32;

    issue_stage(0, 0);

    for (int it = 0; it < NIT; it++) {
        int cur = it & 1;
        if (it + 1 < NIT) {
            issue_stage(cur ^ 1, (it + 1) * 32);
            asm volatile("cp.async.wait_group 1;");
        } else {
            asm volatile("cp.async.wait_group 0;");
        }
        __syncthreads();

        uint32_t sa = smb + cur * STAGE_BYT;
#pragma unroll
        for (int kk = 0; kk < 32; kk += 16) {
            uint32_t ahf[4][4], alf[4][4];
#pragma unroll
            for (int m = 0; m < 4; m++) {
                uint32_t off = ((a_row + m * 16) * LDT + kk + a_colh) * 2;
                ldm_x4(ahf[m], sa + off);
                ldm_x4(alf[m], sa + TILE_BYT + off);
            }
            uint32_t bhf[2][4], blf[2][4];
#pragma unroll
            for (int p = 0; p < 2; p++) {
                uint32_t off = ((b_row + p * 16) * LDT + kk + b_colh) * 2;
                ldm_x4(bhf[p], sa + 2 * TILE_BYT + off);
                ldm_x4(blf[p], sa + 3 * TILE_BYT + off);
            }
#pragma unroll
            for (int m = 0; m < 4; m++) {
#pragma unroll
                for (int n = 0; n < 4; n++) {
                    const uint32_t* b2h = &bhf[n >> 1][(n & 1) * 2];
                    const uint32_t* b2l = &blf[n >> 1][(n & 1) * 2];
                    mma_bf16(acc[m][n], ahf[m], b2h);
                    mma_bf16(acc[m][n], ahf[m], b2l);
                    mma_bf16(acc[m][n], alf[m], b2h);
                }
            }
        }
        __syncthreads();
    }

    // epilogue
    const int g = lane >> 2;
    const int cp = (lane & 3) * 2;
#pragma unroll
    for (int m = 0; m < 4; m++) {
        int row0 = mbase + warpM * 64 + m * 16 + g;
#pragma unroll
        for (int n = 0; n < 4; n++) {
            int col = nbase + warpN * 32 + n * 8 + cp;
            float b0 = 0.f, b1 = 0.f;
            if (BIAS) { b0 = bias[col]; b1 = bias[col + 1]; }
            float2 v0 = make_float2(acc[m][n][0] + b0, acc[m][n][1] + b1);
            float2 v1 = make_float2(acc[m][n][2] + b0, acc[m][n][3] + b1);
            *(float2*)(C + (size_t)row0 * Nc + col) = v0;
            *(float2*)(C + (size_t)(row0 + 8) * Nc + col) = v1;
        }
    }
}

// ---------------------------------------------------------------------------
// l2norm v2: normalize q/k per 64-group and emit bf16 hi/lo in per-head layout
// g_qn*[bh][n][0..63]=q_n, [64..127]=k_n.  One warp per (token, head).
// ---------------------------------------------------------------------------
__global__ __launch_bounds__(256) void l2norm2_kernel(const float* __restrict__ qk)
{
    int w = blockIdx.x * 8 + (threadIdx.x >> 5);   // 0..131071
    int lane = threadIdx.x & 31;
    int tok = w >> 4;
    int h = w & 15;
    int b = tok >> 11;
    int n = tok & 2047;

    const float* qp = qk + (size_t)tok * (2 * CC) + h * HD;
    const float* kp = qp + CC;
    float q0 = qp[lane], q1 = qp[lane + 32];
    float k0 = kp[lane], k1 = kp[lane + 32];
    float sq = q0 * q0 + q1 * q1;
    float sk = k0 * k0 + k1 * k1;
#pragma unroll
    for (int off = 16; off; off >>= 1) {
        sq += __shfl_xor_sync(0xffffffffu, sq, off);
        sk += __shfl_xor_sync(0xffffffffu, sk, off);
    }
    float iq = 1.0f / fmaxf(sqrtf(sq), 1e-12f);
    float ik = 1.0f / fmaxf(sqrtf(sk), 1e-12f);
    q0 *= iq; q1 *= iq; k0 *= ik; k1 *= ik;

    size_t base = ((size_t)(b * HH + h) * NN + n) * 128;
    __nv_bfloat16 h0 = __float2bfloat16(q0);
    __nv_bfloat16 h1 = __float2bfloat16(q1);
    __nv_bfloat16 h2 = __float2bfloat16(k0);
    __nv_bfloat16 h3 = __float2bfloat16(k1);
    g_qnh[base + lane]       = h0;
    g_qnh[base + lane + 32]  = h1;
    g_qnh[base + 64 + lane]  = h2;
    g_qnh[base + 96 + lane]  = h3;
    g_qnl[base + lane]       = __float2bfloat16(q0 - __bfloat162float(h0));
    g_qnl[base + lane + 32]  = __float2bfloat16(q1 - __bfloat162float(h1));
    g_qnl[base + 64 + lane]  = __float2bfloat16(k0 - __bfloat162float(h2));
    g_qnl[base + 96 + lane]  = __float2bfloat16(k1 - __bfloat162float(h3));
}

// ---------------------------------------------------------------------------
// genw: per (b,h) fold subsampled low-rank weights with cw_w -> BW bf16 hi/lo
// ---------------------------------------------------------------------------
__global__ __launch_bounds__(256) void genw_kernel(
    const float* __restrict__ x, const float* __restrict__ we,
    const float* __restrict__ wr, const float* __restrict__ cw_w)
{
    int bh = blockIdx.x;
    int b = bh >> 4, h = bh & 15;
    __shared__ int   idx_s[RR];
    __shared__ float web[HD][LR], wrb[HD][LR];
    int t = threadIdx.x;

    if (t < RR) idx_s[t] = (int)((double)t * (double)(NN - 1) / (double)(RR - 1));
    __syncthreads();

    for (int it = t; it < HD * LR; it += 256) {
        int d = it / LR, e = it % LR;
        float se = 0.f, sr = 0.f;
        for (int r = 0; r < RR; r++) {
            float xv = x[((size_t)b * NN + idx_s[r]) * CC + h * HD + d];
            se += xv * we[((size_t)h * RR + r) * LR + e];
            sr += xv * wr[((size_t)h * RR + r) * LR + e];
        }
        web[d][e] = se;
        wrb[d][e] = sr;
    }
    __syncthreads();

    __nv_bfloat16* bwh = g_bwh + (size_t)bh * HD * 128;
    __nv_bfloat16* bwl = g_bwl + (size_t)bh * HD * 128;
    for (int it = t; it < HD * HD; it += 256) {
        int d = it >> 6, o = it & 63;
        float ae = 0.f, ar = 0.f;
#pragma unroll
        for (int e = 0; e < LR; e++) {
            ae += web[d][e] * cw_w[o * (2 * LR) + e];
            ar += wrb[d][e] * cw_w[o * (2 * LR) + LR + e];
        }
        __nv_bfloat16 ha = __float2bfloat16(ae);
        __nv_bfloat16 hr = __float2bfloat16(ar);
        bwh[o * 128 + d]      = ha;
        bwh[o * 128 + 64 + d] = hr;
        bwl[o * 128 + d]      = __float2bfloat16(ae - __bfloat162float(ha));
        bwl[o * 128 + 64 + d] = __float2bfloat16(ar - __bfloat162float(hr));
    }
}

// ---------------------------------------------------------------------------
// score via HMMA: per bh, attn_tile[256,64] = QK[256,128] @ BW[64,128]^T + cw_b
// 3-term bf16 split; output written directly as bf16 hi/lo (feeds GEMM2).
// ---------------------------------------------------------------------------
#define SC_SMEM ((2 * 256 * LDT + 2 * 64 * LDT) * 2)

__global__ __launch_bounds__(256, 2) void score_mma_kernel(const float* __restrict__ cw_b)
{
    extern __shared__ __nv_bfloat16 ssm[];
    __nv_bfloat16* sAh = ssm;                      // 256*40
    __nv_bfloat16* sAl = ssm + 256 * LDT;
    __nv_bfloat16* sBh = ssm + 2 * 256 * LDT;      // 64*40
    __nv_bfloat16* sBl = ssm + 2 * 256 * LDT + 64 * LDT;

    const int t = threadIdx.x;
    const int lane = t & 31, wid = t >> 5;
    const int warpM = wid >> 1;
    const int warpN = wid & 1;
    const int tileM = blockIdx.x;      // 0..7 (256-token tiles)
    const int bh = blockIdx.y;
    const int b = bh >> 4, h = bh & 15;

    const __nv_bfloat16* Abh = g_qnh + ((size_t)bh * NN + tileM * 256) * 128;
    const __nv_bfloat16* Abl = g_qnl + ((size_t)bh * NN + tileM * 256) * 128;
    const __nv_bfloat16* Bbh = g_bwh + (size_t)bh * HD * 128;
    const __nv_bfloat16* Bbl = g_bwl + (size_t)bh * HD * 128;

    const uint32_t smb = smem_u32(ssm);
    const uint32_t offAl = 256 * LDT * 2;
    const uint32_t offBh = 2 * 256 * LDT * 2;
    const uint32_t offBl = offBh + 64 * LDT * 2;

    float acc[4][4][4];
#pragma unroll
    for (int m = 0; m < 4; m++)
#pragma unroll
        for (int n = 0; n < 4; n++)
#pragma unroll
            for (int j = 0; j < 4; j++) acc[m][n][j] = 0.f;

    const int a_row = warpM * 64 + (lane & 15);
    const int a_colh = (lane >> 4) << 3;
    const int b_row = warpN * 32 + ((lane >> 4) << 3) + (lane & 7);
    const int b_colh = ((lane >> 3) & 1) << 3;

    for (int ck = 0; ck < 4; ck++) {
        int kt = ck * 32;
        if (ck) __syncthreads();
#pragma unroll
        for (int j = 0; j < 4; j++) {
            int idx = t + j * 256;
            int row = idx >> 2, c = idx & 3;
            *(uint4*)(sAh + row * LDT + c * 8) = *(const uint4*)(Abh + (size_t)row * 128 + kt + c * 8);
            *(uint4*)(sAl + row * LDT + c * 8) = *(const uint4*)(Abl + (size_t)row * 128 + kt + c * 8);
        }
        {
            int row = t >> 2, c = t & 3;
            if (row < 64) {
                *(uint4*)(sBh + row * LDT + c * 8) = *(const uint4*)(Bbh + (size_t)row * 128 + kt + c * 8);
                *(uint4*)(sBl + row * LDT + c * 8) = *(const uint4*)(Bbl + (size_t)row * 128 + kt + c * 8);
            }
        }
        __syncthreads();

#pragma unroll
        for (int kk = 0; kk < 32; kk += 16) {
            uint32_t ahf[4][4], alf[4][4];
#pragma unroll
            for (int m = 0; m < 4; m++) {
                uint32_t off = ((a_row + m * 16) * LDT + kk + a_colh) * 2;
                ldm_x4(ahf[m], smb + off);
                ldm_x4(alf[m], smb + offAl + off);
            }
            uint32_t bhf[2][4], blf[2][4];
#pragma unroll
            for (int p = 0; p < 2; p++) {
                uint32_t off = ((b_row + p * 16) * LDT + kk + b_colh) * 2;
                ldm_x4(bhf[p], smb + offBh + off);
                ldm_x4(blf[p], smb + offBl + off);
            }
#pragma unroll
            for (int m = 0; m < 4; m++) {
#pragma unroll
                for (int n = 0; n < 4; n++) {
                    const uint32_t* b2h = &bhf[n >> 1][(n & 1) * 2];
                    const uint32_t* b2l = &blf[n >> 1][(n & 1) * 2];
                    mma_bf16(acc[m][n], ahf[m], b2h);
                    mma_bf16(acc[m][n], ahf[m], b2l);
                    mma_bf16(acc[m][n], alf[m], b2h);
                }
            }
        }
    }

    const int g = lane >> 2;
    const int cp = (lane & 3) * 2;
#pragma unroll
    for (int m = 0; m < 4; m++) {
        int n_tok = tileM * 256 + warpM * 64 + m * 16 + g;
#pragma unroll
        for (int n = 0; n < 4; n++) {
            int col = warpN * 32 + n * 8 + cp;
            float b0 = cw_b[col], b1 = cw_b[col + 1];
            size_t r0 = ((size_t)(b * NN + n_tok)) * CC + h * HD + col;
            size_t r1 = ((size_t)(b * NN + n_tok + 8)) * CC + h * HD + col;
            split_store2(acc[m][n][0] + b0, acc[m][n][1] + b1, g_ah + r0, g_al + r0);
            split_store2(acc[m][n][2] + b0, acc[m][n][3] + b1, g_ah + r1, g_al + r1);
        }
    }
}

// ---------------------------------------------------------------------------
extern "C" void kernel_launch(void* const* d_in, const int* in_sizes, int n_in,
                              void* d_out, int out_size)
{
    const float* x      = (const float*)d_in[0];
    const float* qk_w   = (const float*)d_in[1];
    const float* proj_w = (const float*)d_in[2];
    const float* proj_b = (const float*)d_in[3];
    const float* we     = (const float*)d_in[4];
    const float* wr     = (const float*)d_in[5];
    const float* cw_w   = (const float*)d_in[6];
    const float* cw_b   = (const float*)d_in[7];
    float* out = (float*)d_out;

    void *p_qk, *p_xh, *p_xl, *p_qkwh, *p_qkwl, *p_pwh, *p_pwl, *p_ah, *p_al;
    cudaGetSymbolAddress(&p_qk, g_qk);
    cudaGetSymbolAddress(&p_xh, g_xh);
    cudaGetSymbolAddress(&p_xl, g_xl);
    cudaGetSymbolAddress(&p_qkwh, g_qkwh);
    cudaGetSymbolAddress(&p_qkwl, g_qkwl);
    cudaGetSymbolAddress(&p_pwh, g_pwh);
    cudaGetSymbolAddress(&p_pwl, g_pwl);
    cudaGetSymbolAddress(&p_ah, g_ah);
    cudaGetSymbolAddress(&p_al, g_al);
    float* qk = (float*)p_qk;

    cudaFuncSetAttribute(gemm3h_kernel<false>, cudaFuncAttributeMaxDynamicSharedMemorySize, GEMM_SMEM);
    cudaFuncSetAttribute(gemm3h_kernel<true>,  cudaFuncAttributeMaxDynamicSharedMemorySize, GEMM_SMEM);
    cudaFuncSetAttribute(score_mma_kernel, cudaFuncAttributeMaxDynamicSharedMemorySize, SC_SMEM);

    // 0) split x, qk_w, proj_w to bf16 hi/lo (one launch)
    split3_kernel<<<(N4_TOT + 255) / 256, 256>>>(x, qk_w, proj_w);

    // 1) qk = x @ qk_w^T  (HMMA, bf16 x3, cp.async, 2 CTAs/SM)
    gemm3h_kernel<false><<<dim3(2 * CC / 128, M_TOK / 128), 256, GEMM_SMEM>>>(
        (const __nv_bfloat16*)p_xh, (const __nv_bfloat16*)p_xl,
        (const __nv_bfloat16*)p_qkwh, (const __nv_bfloat16*)p_qkwl,
        nullptr, qk, M_TOK, 2 * CC, CC);

    // 2) normalize q/k -> bf16 hi/lo per-head layout
    l2norm2_kernel<<<(M_TOK * HH) / 8, 256>>>(qk);

    // 3) fold low-rank weights -> BW bf16 hi/lo
    genw_kernel<<<BB * HH, 256>>>(x, we, wr, cw_w);

    // 4) attn = [q|k] @ BW^T + cw_b  (HMMA), output split bf16 hi/lo
    score_mma_kernel<<<dim3(NN / 256, BB * HH), 256, SC_SMEM>>>(cw_b);

    // 5) out = attn @ proj_w^T + proj_b  (HMMA, bf16 x3, cp.async, 2 CTAs/SM)
    gemm3h_kernel<true><<<dim3(CC / 128, M_TOK / 128), 256, GEMM_SMEM>>>(
        (const __nv_bfloat16*)p_ah, (const __nv_bfloat16*)p_al,
        (const __nv_bfloat16*)p_pwh, (const __nv_bfloat16*)p_pwl,
        proj_b, out, M_TOK, CC, CC);
}

// round 15
// speedup vs baseline: 1.1377x; 1.0492x over previous
#include <cuda_runtime.h>
#include <cuda_bf16.h>
#include <cstdint>
#include <stdint.h>
#include <math.h>

// Problem constants (fixed by the dataset)
#define BB 4
#define NN 2048
#define CC 1024
#define HH 16
#define HD 64
#define LR 20
#define RR 200
#define M_TOK (BB * NN)   // 8192 token rows

// ---------------- scratch (__device__ globals; no allocs allowed) -----------
__device__ float g_qk[(size_t)M_TOK * 2 * CC];   // [8192][2048] q|k fp32

__device__ __nv_bfloat16 g_xh[(size_t)M_TOK * CC];
__device__ __nv_bfloat16 g_xl[(size_t)M_TOK * CC];
__device__ __nv_bfloat16 g_qkwh[(size_t)2 * CC * CC];
__device__ __nv_bfloat16 g_qkwl[(size_t)2 * CC * CC];
__device__ __nv_bfloat16 g_pwh[(size_t)CC * CC];
__device__ __nv_bfloat16 g_pwl[(size_t)CC * CC];
__device__ __nv_bfloat16 g_ah[(size_t)M_TOK * CC];   // attn hi (split at source)
__device__ __nv_bfloat16 g_al[(size_t)M_TOK * CC];   // attn lo

// normalized q|k per head, [bh][n][128] (0-63 = q, 64-127 = k), bf16 hi/lo
__device__ __nv_bfloat16 g_qnh[(size_t)BB * HH * NN * 128];
__device__ __nv_bfloat16 g_qnl[(size_t)BB * HH * NN * 128];
// combined per-(b,h) weights [bh][o(64)][d(128)]
__device__ __nv_bfloat16 g_bwh[(size_t)BB * HH * HD * 128];
__device__ __nv_bfloat16 g_bwl[(size_t)BB * HH * HD * 128];

// ---------------- helpers ----------------------------------------------------
__device__ __forceinline__ uint32_t smem_u32(const void* p) {
    uint32_t a;
    asm("{ .reg .u64 t; cvta.to.shared.u64 t, %1; cvt.u32.u64 %0, t; }" : "=r"(a) : "l"(p));
    return a;
}
__device__ __forceinline__ void ldm_x4(uint32_t* r, uint32_t addr) {
    asm volatile("ldmatrix.sync.aligned.m8n8.x4.shared.b16 {%0,%1,%2,%3}, [%4];"
        : "=r"(r[0]), "=r"(r[1]), "=r"(r[2]), "=r"(r[3]) : "r"(addr));
}
__device__ __forceinline__ void mma_bf16(float* c, const uint32_t* a, const uint32_t* b) {
    asm volatile("mma.sync.aligned.m16n8k16.row.col.f32.bf16.bf16.f32 "
        "{%0,%1,%2,%3}, {%4,%5,%6,%7}, {%8,%9}, {%0,%1,%2,%3};"
        : "+f"(c[0]), "+f"(c[1]), "+f"(c[2]), "+f"(c[3])
        : "r"(a[0]), "r"(a[1]), "r"(a[2]), "r"(a[3]), "r"(b[0]), "r"(b[1]));
}
__device__ __forceinline__ void cpasync16(uint32_t dst, const void* src) {
    asm volatile("cp.async.cg.shared.global [%0], [%1], 16;" :: "r"(dst), "l"(src));
}
// split a float pair into bf16 hi/lo pairs and store
__device__ __forceinline__ void split_store2(float a, float b,
                                             __nv_bfloat16* hp, __nv_bfloat16* lp) {
    __nv_bfloat16 h0 = __float2bfloat16(a);
    __nv_bfloat16 h1 = __float2bfloat16(b);
    *(__nv_bfloat162*)hp = __nv_bfloat162(h0, h1);
    *(__nv_bfloat162*)lp = __nv_bfloat162(
        __float2bfloat16(a - __bfloat162float(h0)),
        __float2bfloat16(b - __bfloat162float(h1)));
}

// ---------------------------------------------------------------------------
// merged split: x, qk_w, proj_w -> bf16 hi/lo, one launch.
// ---------------------------------------------------------------------------
#define N4_X   (M_TOK * CC / 4)       // 2,097,152
#define N4_QKW (2 * CC * CC / 4)      //   524,288
#define N4_PW  (CC * CC / 4)          //   262,144
#define N4_TOT (N4_X + N4_QKW + N4_PW)

__global__ __launch_bounds__(256) void split3_kernel(
    const float* __restrict__ x, const float* __restrict__ qkw,
    const float* __restrict__ pw)
{
    int i = blockIdx.x * 256 + threadIdx.x;
    const float* src; __nv_bfloat16 *hi, *lo;
    if (i < N4_X)                { src = x;   hi = g_xh;   lo = g_xl; }
    else if (i < N4_X + N4_QKW)  { i -= N4_X; src = qkw; hi = g_qkwh; lo = g_qkwl; }
    else if (i < N4_TOT)         { i -= N4_X + N4_QKW; src = pw; hi = g_pwh; lo = g_pwl; }
    else return;

    float4 v = ((const float4*)src)[i];
    __nv_bfloat16 h0 = __float2bfloat16(v.x);
    __nv_bfloat16 h1 = __float2bfloat16(v.y);
    __nv_bfloat16 h2 = __float2bfloat16(v.z);
    __nv_bfloat16 h3 = __float2bfloat16(v.w);
    __nv_bfloat162* hp = (__nv_bfloat162*)hi;
    __nv_bfloat162* lp = (__nv_bfloat162*)lo;
    hp[2 * i]     = __nv_bfloat162(h0, h1);
    hp[2 * i + 1] = __nv_bfloat162(h2, h3);
    lp[2 * i]     = __nv_bfloat162(__float2bfloat16(v.x - __bfloat162float(h0)),
                                   __float2bfloat16(v.y - __bfloat162float(h1)));
    lp[2 * i + 1] = __nv_bfloat162(__float2bfloat16(v.z - __bfloat162float(h2)),
                                   __float2bfloat16(v.w - __bfloat162float(h3)));
}

// ---------------------------------------------------------------------------
// HMMA GEMM with bf16 3-term split + cp.async double buffering:
//   C[M,Nc] = (Ah+Al)[M,K] @ (Bh+Bl)[Nc,K]^T  (+ bias)
// 128x128 CTA tile, 8 warps (2x4), warp tile 64x32, BK=32.
// __launch_bounds__(256, 2): 2 CTAs/SM so barrier bubbles overlap across CTAs.
// ---------------------------------------------------------------------------
#define LDT 40
#define TILE_ELE (128 * LDT)
#define TILE_BYT (TILE_ELE * 2)
#define STAGE_BYT (4 * TILE_BYT)
#define GEMM_SMEM (2 * STAGE_BYT)    // 81920 bytes

template <bool BIAS>
__global__ __launch_bounds__(256, 2) void gemm3h_kernel(
    const __nv_bfloat16* __restrict__ Ah, const __nv_bfloat16* __restrict__ Al,
    const __nv_bfloat16* __restrict__ Bh, const __nv_bfloat16* __restrict__ Bl,
    const float* __restrict__ bias, float* __restrict__ C,
    int M, int Nc, int K)
{
    extern __shared__ __nv_bfloat16 smem[];
    const int t = threadIdx.x;
    const int lane = t & 31, wid = t >> 5;
    const int warpM = wid & 1;
    const int warpN = wid >> 1;
    const int mbase = blockIdx.y * 128;
    const int nbase = blockIdx.x * 128;
    const uint32_t smb = smem_u32(smem);

    const __nv_bfloat16* base[4] = {
        Ah + (size_t)mbase * K, Al + (size_t)mbase * K,
        Bh + (size_t)nbase * K, Bl + (size_t)nbase * K };

    const int lr0 = t >> 2;             // 0..63
    const int lc4 = t & 3;              // 16B chunk within 64B row

    float acc[4][4][4];
#pragma unroll
    for (int m = 0; m < 4; m++)
#pragma unroll
        for (int n = 0; n < 4; n++)
#pragma unroll
            for (int j = 0; j < 4; j++) acc[m][n][j] = 0.f;

    auto issue_stage = [&](int s, int kt) {
        uint32_t sb = smb + s * STAGE_BYT;
#pragma unroll
        for (int tl = 0; tl < 4; tl++) {
            const __nv_bfloat16* gp = base[tl] + (size_t)lr0 * K + kt + lc4 * 8;
            uint32_t dp = sb + tl * TILE_BYT + (lr0 * LDT + lc4 * 8) * 2;
            cpasync16(dp, gp);
            cpasync16(dp + 64 * LDT * 2, gp + (size_t)64 * K);
        }
        asm volatile("cp.async.commit_group;");
    };

    const int a_row = warpM * 64 + (lane & 15);
    const int a_colh = (lane >> 4) << 3;
    const int b_row = warpN * 32 + ((lane >> 4) << 3) + (lane & 7);
    const int b_colh = ((lane >> 3) & 1) << 3;

    const int NIT = K / 32;

    issue_stage(0, 0);

    for (int it = 0; it < NIT; it++) {
        int cur = it & 1;
        if (it + 1 < NIT) {
            issue_stage(cur ^ 1, (it + 1) * 32);
            asm volatile("cp.async.wait_group 1;");
        } else {
            asm volatile("cp.async.wait_group 0;");
        }
        __syncthreads();

        uint32_t sa = smb + cur * STAGE_BYT;
#pragma unroll
        for (int kk = 0; kk < 32; kk += 16) {
            uint32_t ahf[4][4], alf[4][4];
#pragma unroll
            for (int m = 0; m < 4; m++) {
                uint32_t off = ((a_row + m * 16) * LDT + kk + a_colh) * 2;
                ldm_x4(ahf[m], sa + off);
                ldm_x4(alf[m], sa + TILE_BYT + off);
            }
            uint32_t bhf[2][4], blf[2][4];
#pragma unroll
            for (int p = 0; p < 2; p++) {
                uint32_t off = ((b_row + p * 16) * LDT + kk + b_colh) * 2;
                ldm_x4(bhf[p], sa + 2 * TILE_BYT + off);
                ldm_x4(blf[p], sa + 3 * TILE_BYT + off);
            }
#pragma unroll
            for (int m = 0; m < 4; m++) {
#pragma unroll
                for (int n = 0; n < 4; n++) {
                    const uint32_t* b2h = &bhf[n >> 1][(n & 1) * 2];
                    const uint32_t* b2l = &blf[n >> 1][(n & 1) * 2];
                    mma_bf16(acc[m][n], ahf[m], b2h);
                    mma_bf16(acc[m][n], ahf[m], b2l);
                    mma_bf16(acc[m][n], alf[m], b2h);
                }
            }
        }
        __syncthreads();
    }

    // epilogue
    const int g = lane >> 2;
    const int cp = (lane & 3) * 2;
#pragma unroll
    for (int m = 0; m < 4; m++) {
        int row0 = mbase + warpM * 64 + m * 16 + g;
#pragma unroll
        for (int n = 0; n < 4; n++) {
            int col = nbase + warpN * 32 + n * 8 + cp;
            float b0 = 0.f, b1 = 0.f;
            if (BIAS) { b0 = bias[col]; b1 = bias[col + 1]; }
            float2 v0 = make_float2(acc[m][n][0] + b0, acc[m][n][1] + b1);
            float2 v1 = make_float2(acc[m][n][2] + b0, acc[m][n][3] + b1);
            *(float2*)(C + (size_t)row0 * Nc + col) = v0;
            *(float2*)(C + (size_t)(row0 + 8) * Nc + col) = v1;
        }
    }
}

// ---------------------------------------------------------------------------
// l2norm v2: normalize q/k per 64-group and emit bf16 hi/lo in per-head layout
// ---------------------------------------------------------------------------
__global__ __launch_bounds__(256) void l2norm2_kernel(const float* __restrict__ qk)
{
    int w = blockIdx.x * 8 + (threadIdx.x >> 5);   // 0..131071
    int lane = threadIdx.x & 31;
    int tok = w >> 4;
    int h = w & 15;
    int b = tok >> 11;
    int n = tok & 2047;

    const float* qp = qk + (size_t)tok * (2 * CC) + h * HD;
    const float* kp = qp + CC;
    float q0 = qp[lane], q1 = qp[lane + 32];
    float k0 = kp[lane], k1 = kp[lane + 32];
    float sq = q0 * q0 + q1 * q1;
    float sk = k0 * k0 + k1 * k1;
#pragma unroll
    for (int off = 16; off; off >>= 1) {
        sq += __shfl_xor_sync(0xffffffffu, sq, off);
        sk += __shfl_xor_sync(0xffffffffu, sk, off);
    }
    float iq = 1.0f / fmaxf(sqrtf(sq), 1e-12f);
    float ik = 1.0f / fmaxf(sqrtf(sk), 1e-12f);
    q0 *= iq; q1 *= iq; k0 *= ik; k1 *= ik;

    size_t base = ((size_t)(b * HH + h) * NN + n) * 128;
    __nv_bfloat16 h0 = __float2bfloat16(q0);
    __nv_bfloat16 h1 = __float2bfloat16(q1);
    __nv_bfloat16 h2 = __float2bfloat16(k0);
    __nv_bfloat16 h3 = __float2bfloat16(k1);
    g_qnh[base + lane]       = h0;
    g_qnh[base + lane + 32]  = h1;
    g_qnh[base + 64 + lane]  = h2;
    g_qnh[base + 96 + lane]  = h3;
    g_qnl[base + lane]       = __float2bfloat16(q0 - __bfloat162float(h0));
    g_qnl[base + lane + 32]  = __float2bfloat16(q1 - __bfloat162float(h1));
    g_qnl[base + 64 + lane]  = __float2bfloat16(k0 - __bfloat162float(h2));
    g_qnl[base + 96 + lane]  = __float2bfloat16(k1 - __bfloat162float(h3));
}

// ---------------------------------------------------------------------------
// genw v3: smem-staged, grid = (64 bh, 2 d-halves).
// Phase 1: stage xs[200][32] (each x element read ONCE, coalesced),
//          we/wr [200][20], cw_w [64][40] into dynamic smem.
// Phase 2: web/wrb[d][e] = sum_r xs[r][d] * we/wr[r][e]   (identical r-order)
// Phase 3: fold with cw_w -> BW bf16 hi/lo (d-half only).
// ---------------------------------------------------------------------------
#define GENW_F (RR * 32 + 2 * RR * LR + 2 * 32 * LR + HD * 2 * LR) // 18240 floats
#define GENW_SMEM (GENW_F * 4)                                     // 72960 bytes

__global__ __launch_bounds__(256) void genw_kernel(
    const float* __restrict__ x, const float* __restrict__ we,
    const float* __restrict__ wr, const float* __restrict__ cw_w)
{
    extern __shared__ float gs[];
    float* xs  = gs;                         // [RR][32]
    float* wes = xs + RR * 32;               // [RR][LR]
    float* wrs = wes + RR * LR;              // [RR][LR]
    float* web = wrs + RR * LR;              // [32][LR]
    float* wrb = web + 32 * LR;              // [32][LR]
    float* cws = wrb + 32 * LR;              // [HD][2*LR]

    const int bh = blockIdx.x;
    const int half = blockIdx.y;             // d-half: 0 or 1
    const int b = bh >> 4, h = bh & 15;
    const int dbase = half * 32;
    const int t = threadIdx.x;

    // stage x at 200 sampled positions (32-wide coalesced)
    for (int i = t; i < RR * 32; i += 256) {
        int r = i >> 5, d = i & 31;
        int idx = (int)((double)r * (double)(NN - 1) / (double)(RR - 1));
        xs[i] = x[((size_t)b * NN + idx) * CC + h * HD + dbase + d];
    }
    // stage we / wr for this head
    for (int i = t; i < RR * LR; i += 256) {
        wes[i] = we[(size_t)h * RR * LR + i];
        wrs[i] = wr[(size_t)h * RR * LR + i];
    }
    // stage cw_w
    for (int i = t; i < HD * 2 * LR; i += 256) cws[i] = cw_w[i];
    __syncthreads();

    // phase 2: 32*20 = 640 outputs, r-order identical to original
    for (int it = t; it < 32 * LR; it += 256) {
        int d = it / LR, e = it % LR;
        float se = 0.f, sr = 0.f;
        for (int r = 0; r < RR; r++) {
            float xv = xs[r * 32 + d];
            se += xv * wes[r * LR + e];
            sr += xv * wrs[r * LR + e];
        }
        web[d * LR + e] = se;
        wrb[d * LR + e] = sr;
    }
    __syncthreads();

    // phase 3: 32*64 = 2048 outputs for this d-half
    __nv_bfloat16* bwh = g_bwh + (size_t)bh * HD * 128;
    __nv_bfloat16* bwl = g_bwl + (size_t)bh * HD * 128;
    for (int it = t; it < 32 * HD; it += 256) {
        int d = it >> 6, o = it & 63;        // d local 0..31
        float ae = 0.f, ar = 0.f;
#pragma unroll
        for (int e = 0; e < LR; e++) {
            ae += web[d * LR + e] * cws[o * (2 * LR) + e];
            ar += wrb[d * LR + e] * cws[o * (2 * LR) + LR + e];
        }
        int dg = dbase + d;
        __nv_bfloat16 ha = __float2bfloat16(ae);
        __nv_bfloat16 hr = __float2bfloat16(ar);
        bwh[o * 128 + dg]      = ha;
        bwh[o * 128 + 64 + dg] = hr;
        bwl[o * 128 + dg]      = __float2bfloat16(ae - __bfloat162float(ha));
        bwl[o * 128 + 64 + dg] = __float2bfloat16(ar - __bfloat162float(hr));
    }
}

// ---------------------------------------------------------------------------
// score via HMMA: per bh, attn_tile[256,64] = QK[256,128] @ BW[64,128]^T + cw_b
// 3-term bf16 split; output written directly as bf16 hi/lo (feeds GEMM2).
// ---------------------------------------------------------------------------
#define SC_SMEM ((2 * 256 * LDT + 2 * 64 * LDT) * 2)

__global__ __launch_bounds__(256, 2) void score_mma_kernel(const float* __restrict__ cw_b)
{
    extern __shared__ __nv_bfloat16 ssm[];
    __nv_bfloat16* sAh = ssm;                      // 256*40
    __nv_bfloat16* sAl = ssm + 256 * LDT;
    __nv_bfloat16* sBh = ssm + 2 * 256 * LDT;      // 64*40
    __nv_bfloat16* sBl = ssm + 2 * 256 * LDT + 64 * LDT;

    const int t = threadIdx.x;
    const int lane = t & 31, wid = t >> 5;
    const int warpM = wid >> 1;
    const int warpN = wid & 1;
    const int tileM = blockIdx.x;      // 0..7 (256-token tiles)
    const int bh = blockIdx.y;
    const int b = bh >> 4, h = bh & 15;

    const __nv_bfloat16* Abh = g_qnh + ((size_t)bh * NN + tileM * 256) * 128;
    const __nv_bfloat16* Abl = g_qnl + ((size_t)bh * NN + tileM * 256) * 128;
    const __nv_bfloat16* Bbh = g_bwh + (size_t)bh * HD * 128;
    const __nv_bfloat16* Bbl = g_bwl + (size_t)bh * HD * 128;

    const uint32_t smb = smem_u32(ssm);
    const uint32_t offAl = 256 * LDT * 2;
    const uint32_t offBh = 2 * 256 * LDT * 2;
    const uint32_t offBl = offBh + 64 * LDT * 2;

    float acc[4][4][4];
#pragma unroll
    for (int m = 0; m < 4; m++)
#pragma unroll
        for (int n = 0; n < 4; n++)
#pragma unroll
            for (int j = 0; j < 4; j++) acc[m][n][j] = 0.f;

    const int a_row = warpM * 64 + (lane & 15);
    const int a_colh = (lane >> 4) << 3;
    const int b_row = warpN * 32 + ((lane >> 4) << 3) + (lane & 7);
    const int b_colh = ((lane >> 3) & 1) << 3;

    for (int ck = 0; ck < 4; ck++) {
        int kt = ck * 32;
        if (ck) __syncthreads();
#pragma unroll
        for (int j = 0; j < 4; j++) {
            int idx = t + j * 256;
            int row = idx >> 2, c = idx & 3;
            *(uint4*)(sAh + row * LDT + c * 8) = *(const uint4*)(Abh + (size_t)row * 128 + kt + c * 8);
            *(uint4*)(sAl + row * LDT + c * 8) = *(const uint4*)(Abl + (size_t)row * 128 + kt + c * 8);
        }
        {
            int row = t >> 2, c = t & 3;
            if (row < 64) {
                *(uint4*)(sBh + row * LDT + c * 8) = *(const uint4*)(Bbh + (size_t)row * 128 + kt + c * 8);
                *(uint4*)(sBl + row * LDT + c * 8) = *(const uint4*)(Bbl + (size_t)row * 128 + kt + c * 8);
            }
        }
        __syncthreads();

#pragma unroll
        for (int kk = 0; kk < 32; kk += 16) {
            uint32_t ahf[4][4], alf[4][4];
#pragma unroll
            for (int m = 0; m < 4; m++) {
                uint32_t off = ((a_row + m * 16) * LDT + kk + a_colh) * 2;
                ldm_x4(ahf[m], smb + off);
                ldm_x4(alf[m], smb + offAl + off);
            }
            uint32_t bhf[2][4], blf[2][4];
#pragma unroll
            for (int p = 0; p < 2; p++) {
                uint32_t off = ((b_row + p * 16) * LDT + kk + b_colh) * 2;
                ldm_x4(bhf[p], smb + offBh + off);
                ldm_x4(blf[p], smb + offBl + off);
            }
#pragma unroll
            for (int m = 0; m < 4; m++) {
#pragma unroll
                for (int n = 0; n < 4; n++) {
                    const uint32_t* b2h = &bhf[n >> 1][(n & 1) * 2];
                    const uint32_t* b2l = &blf[n >> 1][(n & 1) * 2];
                    mma_bf16(acc[m][n], ahf[m], b2h);
                    mma_bf16(acc[m][n], ahf[m], b2l);
                    mma_bf16(acc[m][n], alf[m], b2h);
                }
            }
        }
    }

    const int g = lane >> 2;
    const int cp = (lane & 3) * 2;
#pragma unroll
    for (int m = 0; m < 4; m++) {
        int n_tok = tileM * 256 + warpM * 64 + m * 16 + g;
#pragma unroll
        for (int n = 0; n < 4; n++) {
            int col = warpN * 32 + n * 8 + cp;
            float b0 = cw_b[col], b1 = cw_b[col + 1];
            size_t r0 = ((size_t)(b * NN + n_tok)) * CC + h * HD + col;
            size_t r1 = ((size_t)(b * NN + n_tok + 8)) * CC + h * HD + col;
            split_store2(acc[m][n][0] + b0, acc[m][n][1] + b1, g_ah + r0, g_al + r0);
            split_store2(acc[m][n][2] + b0, acc[m][n][3] + b1, g_ah + r1, g_al + r1);
        }
    }
}

// ---------------------------------------------------------------------------
extern "C" void kernel_launch(void* const* d_in, const int* in_sizes, int n_in,
                              void* d_out, int out_size)
{
    const float* x      = (const float*)d_in[0];
    const float* qk_w   = (const float*)d_in[1];
    const float* proj_w = (const float*)d_in[2];
    const float* proj_b = (const float*)d_in[3];
    const float* we     = (const float*)d_in[4];
    const float* wr     = (const float*)d_in[5];
    const float* cw_w   = (const float*)d_in[6];
    const float* cw_b   = (const float*)d_in[7];
    float* out = (float*)d_out;

    void *p_qk, *p_xh, *p_xl, *p_qkwh, *p_qkwl, *p_pwh, *p_pwl, *p_ah, *p_al;
    cudaGetSymbolAddress(&p_qk, g_qk);
    cudaGetSymbolAddress(&p_xh, g_xh);
    cudaGetSymbolAddress(&p_xl, g_xl);
    cudaGetSymbolAddress(&p_qkwh, g_qkwh);
    cudaGetSymbolAddress(&p_qkwl, g_qkwl);
    cudaGetSymbolAddress(&p_pwh, g_pwh);
    cudaGetSymbolAddress(&p_pwl, g_pwl);
    cudaGetSymbolAddress(&p_ah, g_ah);
    cudaGetSymbolAddress(&p_al, g_al);
    float* qk = (float*)p_qk;

    cudaFuncSetAttribute(gemm3h_kernel<false>, cudaFuncAttributeMaxDynamicSharedMemorySize, GEMM_SMEM);
    cudaFuncSetAttribute(gemm3h_kernel<true>,  cudaFuncAttributeMaxDynamicSharedMemorySize, GEMM_SMEM);
    cudaFuncSetAttribute(score_mma_kernel, cudaFuncAttributeMaxDynamicSharedMemorySize, SC_SMEM);
    cudaFuncSetAttribute(genw_kernel, cudaFuncAttributeMaxDynamicSharedMemorySize, GENW_SMEM);

    // 0) split x, qk_w, proj_w to bf16 hi/lo (one launch)
    split3_kernel<<<(N4_TOT + 255) / 256, 256>>>(x, qk_w, proj_w);

    // 1) qk = x @ qk_w^T  (HMMA, bf16 x3, cp.async, 2 CTAs/SM)
    gemm3h_kernel<false><<<dim3(2 * CC / 128, M_TOK / 128), 256, GEMM_SMEM>>>(
        (const __nv_bfloat16*)p_xh, (const __nv_bfloat16*)p_xl,
        (const __nv_bfloat16*)p_qkwh, (const __nv_bfloat16*)p_qkwl,
        nullptr, qk, M_TOK, 2 * CC, CC);

    // 2) normalize q/k -> bf16 hi/lo per-head layout
    l2norm2_kernel<<<(M_TOK * HH) / 8, 256>>>(qk);

    // 3) fold low-rank weights -> BW bf16 hi/lo (smem-staged, 128 CTAs)
    genw_kernel<<<dim3(BB * HH, 2), 256, GENW_SMEM>>>(x, we, wr, cw_w);

    // 4) attn = [q|k] @ BW^T + cw_b  (HMMA), output split bf16 hi/lo
    score_mma_kernel<<<dim3(NN / 256, BB * HH), 256, SC_SMEM>>>(cw_b);

    // 5) out = attn @ proj_w^T + proj_b  (HMMA, bf16 x3, cp.async, 2 CTAs/SM)
    gemm3h_kernel<true><<<dim3(CC / 128, M_TOK / 128), 256, GEMM_SMEM>>>(
        (const __nv_bfloat16*)p_ah, (const __nv_bfloat16*)p_al,
        (const __nv_bfloat16*)p_pwh, (const __nv_bfloat16*)p_pwl,
        proj_b, out, M_TOK, CC, CC);
}

// round 16
// speedup vs baseline: 1.1793x; 1.0366x over previous
#include <cuda_runtime.h>
#include <cuda_bf16.h>
#include <cstdint>
#include <stdint.h>
#include <math.h>

// Problem constants (fixed by the dataset)
#define BB 4
#define NN 2048
#define CC 1024
#define HH 16
#define HD 64
#define LR 20
#define RR 200
#define M_TOK (BB * NN)   // 8192 token rows

// ---------------- scratch (__device__ globals; no allocs allowed) -----------
__device__ float g_qk[(size_t)M_TOK * 2 * CC];   // [8192][2048] q|k fp32

__device__ __nv_bfloat16 g_xh[(size_t)M_TOK * CC];
__device__ __nv_bfloat16 g_xl[(size_t)M_TOK * CC];
__device__ __nv_bfloat16 g_qkwh[(size_t)2 * CC * CC];
__device__ __nv_bfloat16 g_qkwl[(size_t)2 * CC * CC];
__device__ __nv_bfloat16 g_pwh[(size_t)CC * CC];
__device__ __nv_bfloat16 g_pwl[(size_t)CC * CC];
__device__ __nv_bfloat16 g_ah[(size_t)M_TOK * CC];   // attn hi (split at source)
__device__ __nv_bfloat16 g_al[(size_t)M_TOK * CC];   // attn lo

// normalized q|k per head, [bh][n][128] (0-63 = q, 64-127 = k), bf16 hi/lo
__device__ __nv_bfloat16 g_qnh[(size_t)BB * HH * NN * 128];
__device__ __nv_bfloat16 g_qnl[(size_t)BB * HH * NN * 128];
// combined per-(b,h) weights [bh][o(64)][d(128)]
__device__ __nv_bfloat16 g_bwh[(size_t)BB * HH * HD * 128];
__device__ __nv_bfloat16 g_bwl[(size_t)BB * HH * HD * 128];

// ---------------- helpers ----------------------------------------------------
__device__ __forceinline__ uint32_t smem_u32(const void* p) {
    uint32_t a;
    asm("{ .reg .u64 t; cvta.to.shared.u64 t, %1; cvt.u32.u64 %0, t; }" : "=r"(a) : "l"(p));
    return a;
}
__device__ __forceinline__ void ldm_x4(uint32_t* r, uint32_t addr) {
    asm volatile("ldmatrix.sync.aligned.m8n8.x4.shared.b16 {%0,%1,%2,%3}, [%4];"
        : "=r"(r[0]), "=r"(r[1]), "=r"(r[2]), "=r"(r[3]) : "r"(addr));
}
__device__ __forceinline__ void mma_bf16(float* c, const uint32_t* a, const uint32_t* b) {
    asm volatile("mma.sync.aligned.m16n8k16.row.col.f32.bf16.bf16.f32 "
        "{%0,%1,%2,%3}, {%4,%5,%6,%7}, {%8,%9}, {%0,%1,%2,%3};"
        : "+f"(c[0]), "+f"(c[1]), "+f"(c[2]), "+f"(c[3])
        : "r"(a[0]), "r"(a[1]), "r"(a[2]), "r"(a[3]), "r"(b[0]), "r"(b[1]));
}
__device__ __forceinline__ void cpasync16(uint32_t dst, const void* src) {
    asm volatile("cp.async.cg.shared.global [%0], [%1], 16;" :: "r"(dst), "l"(src));
}
// split a float pair into bf16 hi/lo pairs and store
__device__ __forceinline__ void split_store2(float a, float b,
                                             __nv_bfloat16* hp, __nv_bfloat16* lp) {
    __nv_bfloat16 h0 = __float2bfloat16(a);
    __nv_bfloat16 h1 = __float2bfloat16(b);
    *(__nv_bfloat162*)hp = __nv_bfloat162(h0, h1);
    *(__nv_bfloat162*)lp = __nv_bfloat162(
        __float2bfloat16(a - __bfloat162float(h0)),
        __float2bfloat16(b - __bfloat162float(h1)));
}

// ---------------------------------------------------------------------------
// merged split: x, qk_w, proj_w -> bf16 hi/lo, one launch.
// ---------------------------------------------------------------------------
#define N4_X   (M_TOK * CC / 4)       // 2,097,152
#define N4_QKW (2 * CC * CC / 4)      //   524,288
#define N4_PW  (CC * CC / 4)          //   262,144
#define N4_TOT (N4_X + N4_QKW + N4_PW)

__global__ __launch_bounds__(256) void split3_kernel(
    const float* __restrict__ x, const float* __restrict__ qkw,
    const float* __restrict__ pw)
{
    int i = blockIdx.x * 256 + threadIdx.x;
    const float* src; __nv_bfloat16 *hi, *lo;
    if (i < N4_X)                { src = x;   hi = g_xh;   lo = g_xl; }
    else if (i < N4_X + N4_QKW)  { i -= N4_X; src = qkw; hi = g_qkwh; lo = g_qkwl; }
    else if (i < N4_TOT)         { i -= N4_X + N4_QKW; src = pw; hi = g_pwh; lo = g_pwl; }
    else return;

    float4 v = ((const float4*)src)[i];
    __nv_bfloat16 h0 = __float2bfloat16(v.x);
    __nv_bfloat16 h1 = __float2bfloat16(v.y);
    __nv_bfloat16 h2 = __float2bfloat16(v.z);
    __nv_bfloat16 h3 = __float2bfloat16(v.w);
    __nv_bfloat162* hp = (__nv_bfloat162*)hi;
    __nv_bfloat162* lp = (__nv_bfloat162*)lo;
    hp[2 * i]     = __nv_bfloat162(h0, h1);
    hp[2 * i + 1] = __nv_bfloat162(h2, h3);
    lp[2 * i]     = __nv_bfloat162(__float2bfloat16(v.x - __bfloat162float(h0)),
                                   __float2bfloat16(v.y - __bfloat162float(h1)));
    lp[2 * i + 1] = __nv_bfloat162(__float2bfloat16(v.z - __bfloat162float(h2)),
                                   __float2bfloat16(v.w - __bfloat162float(h3)));
}

// ---------------------------------------------------------------------------
// HMMA GEMM with bf16 3-term split + cp.async double buffering:
//   C[M,Nc] = (Ah+Al)[M,K] @ (Bh+Bl)[Nc,K]^T  (+ bias)
// 128x128 CTA tile, 8 warps (2x4), warp tile 64x32, BK=32.
// __launch_bounds__(256, 2): 2 CTAs/SM so barrier bubbles overlap across CTAs.
// ---------------------------------------------------------------------------
#define LDT 40
#define TILE_ELE (128 * LDT)
#define TILE_BYT (TILE_ELE * 2)
#define STAGE_BYT (4 * TILE_BYT)
#define GEMM_SMEM (2 * STAGE_BYT)    // 81920 bytes

template <bool BIAS>
__global__ __launch_bounds__(256, 2) void gemm3h_kernel(
    const __nv_bfloat16* __restrict__ Ah, const __nv_bfloat16* __restrict__ Al,
    const __nv_bfloat16* __restrict__ Bh, const __nv_bfloat16* __restrict__ Bl,
    const float* __restrict__ bias, float* __restrict__ C,
    int M, int Nc, int K)
{
    extern __shared__ __nv_bfloat16 smem[];
    const int t = threadIdx.x;
    const int lane = t & 31, wid = t >> 5;
    const int warpM = wid & 1;
    const int warpN = wid >> 1;
    const int mbase = blockIdx.y * 128;
    const int nbase = blockIdx.x * 128;
    const uint32_t smb = smem_u32(smem);

    const __nv_bfloat16* base[4] = {
        Ah + (size_t)mbase * K, Al + (size_t)mbase * K,
        Bh + (size_t)nbase * K, Bl + (size_t)nbase * K };

    const int lr0 = t >> 2;             // 0..63
    const int lc4 = t & 3;              // 16B chunk within 64B row

    float acc[4][4][4];
#pragma unroll
    for (int m = 0; m < 4; m++)
#pragma unroll
        for (int n = 0; n < 4; n++)
#pragma unroll
            for (int j = 0; j < 4; j++) acc[m][n][j] = 0.f;

    auto issue_stage = [&](int s, int kt) {
        uint32_t sb = smb + s * STAGE_BYT;
#pragma unroll
        for (int tl = 0; tl < 4; tl++) {
            const __nv_bfloat16* gp = base[tl] + (size_t)lr0 * K + kt + lc4 * 8;
            uint32_t dp = sb + tl * TILE_BYT + (lr0 * LDT + lc4 * 8) * 2;
            cpasync16(dp, gp);
            cpasync16(dp + 64 * LDT * 2, gp + (size_t)64 * K);
        }
        asm volatile("cp.async.commit_group;");
    };

    const int a_row = warpM * 64 + (lane & 15);
    const int a_colh = (lane >> 4) << 3;
    const int b_row = warpN * 32 + ((lane >> 4) << 3) + (lane & 7);
    const int b_colh = ((lane >> 3) & 1) << 3;

    const int NIT = K / 32;

    issue_stage(0, 0);

    for (int it = 0; it < NIT; it++) {
        int cur = it & 1;
        if (it + 1 < NIT) {
            issue_stage(cur ^ 1, (it + 1) * 32);
            asm volatile("cp.async.wait_group 1;");
        } else {
            asm volatile("cp.async.wait_group 0;");
        }
        __syncthreads();

        uint32_t sa = smb + cur * STAGE_BYT;
#pragma unroll
        for (int kk = 0; kk < 32; kk += 16) {
            uint32_t ahf[4][4], alf[4][4];
#pragma unroll
            for (int m = 0; m < 4; m++) {
                uint32_t off = ((a_row + m * 16) * LDT + kk + a_colh) * 2;
                ldm_x4(ahf[m], sa + off);
                ldm_x4(alf[m], sa + TILE_BYT + off);
            }
            uint32_t bhf[2][4], blf[2][4];
#pragma unroll
            for (int p = 0; p < 2; p++) {
                uint32_t off = ((b_row + p * 16) * LDT + kk + b_colh) * 2;
                ldm_x4(bhf[p], sa + 2 * TILE_BYT + off);
                ldm_x4(blf[p], sa + 3 * TILE_BYT + off);
            }
#pragma unroll
            for (int m = 0; m < 4; m++) {
#pragma unroll
                for (int n = 0; n < 4; n++) {
                    const uint32_t* b2h = &bhf[n >> 1][(n & 1) * 2];
                    const uint32_t* b2l = &blf[n >> 1][(n & 1) * 2];
                    mma_bf16(acc[m][n], ahf[m], b2h);
                    mma_bf16(acc[m][n], ahf[m], b2l);
                    mma_bf16(acc[m][n], alf[m], b2h);
                }
            }
        }
        __syncthreads();
    }

    // epilogue
    const int g = lane >> 2;
    const int cp = (lane & 3) * 2;
#pragma unroll
    for (int m = 0; m < 4; m++) {
        int row0 = mbase + warpM * 64 + m * 16 + g;
#pragma unroll
        for (int n = 0; n < 4; n++) {
            int col = nbase + warpN * 32 + n * 8 + cp;
            float b0 = 0.f, b1 = 0.f;
            if (BIAS) { b0 = bias[col]; b1 = bias[col + 1]; }
            float2 v0 = make_float2(acc[m][n][0] + b0, acc[m][n][1] + b1);
            float2 v1 = make_float2(acc[m][n][2] + b0, acc[m][n][3] + b1);
            *(float2*)(C + (size_t)row0 * Nc + col) = v0;
            *(float2*)(C + (size_t)(row0 + 8) * Nc + col) = v1;
        }
    }
}

// ---------------------------------------------------------------------------
// l2norm v2: normalize q/k per 64-group and emit bf16 hi/lo in per-head layout
// ---------------------------------------------------------------------------
__global__ __launch_bounds__(256) void l2norm2_kernel(const float* __restrict__ qk)
{
    int w = blockIdx.x * 8 + (threadIdx.x >> 5);   // 0..131071
    int lane = threadIdx.x & 31;
    int tok = w >> 4;
    int h = w & 15;
    int b = tok >> 11;
    int n = tok & 2047;

    const float* qp = qk + (size_t)tok * (2 * CC) + h * HD;
    const float* kp = qp + CC;
    float q0 = qp[lane], q1 = qp[lane + 32];
    float k0 = kp[lane], k1 = kp[lane + 32];
    float sq = q0 * q0 + q1 * q1;
    float sk = k0 * k0 + k1 * k1;
#pragma unroll
    for (int off = 16; off; off >>= 1) {
        sq += __shfl_xor_sync(0xffffffffu, sq, off);
        sk += __shfl_xor_sync(0xffffffffu, sk, off);
    }
    float iq = 1.0f / fmaxf(sqrtf(sq), 1e-12f);
    float ik = 1.0f / fmaxf(sqrtf(sk), 1e-12f);
    q0 *= iq; q1 *= iq; k0 *= ik; k1 *= ik;

    size_t base = ((size_t)(b * HH + h) * NN + n) * 128;
    __nv_bfloat16 h0 = __float2bfloat16(q0);
    __nv_bfloat16 h1 = __float2bfloat16(q1);
    __nv_bfloat16 h2 = __float2bfloat16(k0);
    __nv_bfloat16 h3 = __float2bfloat16(k1);
    g_qnh[base + lane]       = h0;
    g_qnh[base + lane + 32]  = h1;
    g_qnh[base + 64 + lane]  = h2;
    g_qnh[base + 96 + lane]  = h3;
    g_qnl[base + lane]       = __float2bfloat16(q0 - __bfloat162float(h0));
    g_qnl[base + lane + 32]  = __float2bfloat16(q1 - __bfloat162float(h1));
    g_qnl[base + 64 + lane]  = __float2bfloat16(k0 - __bfloat162float(h2));
    g_qnl[base + 96 + lane]  = __float2bfloat16(k1 - __bfloat162float(h3));
}

// ---------------------------------------------------------------------------
// genw v4: smem-staged, grid = (64 bh, 2 d-halves).
// Phase 1: stage xs[200][32] (integer sample index; each x element read once),
//          we/wr [200][20], cw_w [64][40] into dynamic smem.
// Phase 2: 4-way unrolled r-reduction (8 independent accumulators/thread)
//          -> dependency chain 200 -> 50 iterations.
// Phase 3: fold with cw_w -> BW bf16 hi/lo (d-half only).
// ---------------------------------------------------------------------------
#define GENW_F (RR * 32 + 2 * RR * LR + 2 * 32 * LR + HD * 2 * LR) // 18240 floats
#define GENW_SMEM (GENW_F * 4)                                     // 72960 bytes

__global__ __launch_bounds__(256) void genw_kernel(
    const float* __restrict__ x, const float* __restrict__ we,
    const float* __restrict__ wr, const float* __restrict__ cw_w)
{
    extern __shared__ float gs[];
    float* xs  = gs;                         // [RR][32]
    float* wes = xs + RR * 32;               // [RR][LR]
    float* wrs = wes + RR * LR;              // [RR][LR]
    float* web = wrs + RR * LR;              // [32][LR]
    float* wrb = web + 32 * LR;              // [32][LR]
    float* cws = wrb + 32 * LR;              // [HD][2*LR]

    const int bh = blockIdx.x;
    const int half = blockIdx.y;             // d-half: 0 or 1
    const int b = bh >> 4, h = bh & 15;
    const int dbase = half * 32;
    const int t = threadIdx.x;

    // stage x at 200 sampled positions (32-wide coalesced, integer index)
    for (int i = t; i < RR * 32; i += 256) {
        int r = i >> 5, d = i & 31;
        int idx = (r * (NN - 1)) / (RR - 1);     // exact floor, matches trunc(double)
        xs[i] = x[((size_t)b * NN + idx) * CC + h * HD + dbase + d];
    }
    // stage we / wr for this head
    for (int i = t; i < RR * LR; i += 256) {
        wes[i] = we[(size_t)h * RR * LR + i];
        wrs[i] = wr[(size_t)h * RR * LR + i];
    }
    // stage cw_w
    for (int i = t; i < HD * 2 * LR; i += 256) cws[i] = cw_w[i];
    __syncthreads();

    // phase 2: 32*20 = 640 outputs; 4-way unrolled reduction
    for (int it = t; it < 32 * LR; it += 256) {
        int d = it / LR, e = it % LR;
        float se0 = 0.f, se1 = 0.f, se2 = 0.f, se3 = 0.f;
        float sr0 = 0.f, sr1 = 0.f, sr2 = 0.f, sr3 = 0.f;
#pragma unroll 2
        for (int r = 0; r < RR; r += 4) {
            float x0 = xs[(r + 0) * 32 + d];
            float x1 = xs[(r + 1) * 32 + d];
            float x2 = xs[(r + 2) * 32 + d];
            float x3 = xs[(r + 3) * 32 + d];
            se0 += x0 * wes[(r + 0) * LR + e];
            se1 += x1 * wes[(r + 1) * LR + e];
            se2 += x2 * wes[(r + 2) * LR + e];
            se3 += x3 * wes[(r + 3) * LR + e];
            sr0 += x0 * wrs[(r + 0) * LR + e];
            sr1 += x1 * wrs[(r + 1) * LR + e];
            sr2 += x2 * wrs[(r + 2) * LR + e];
            sr3 += x3 * wrs[(r + 3) * LR + e];
        }
        web[d * LR + e] = (se0 + se1) + (se2 + se3);
        wrb[d * LR + e] = (sr0 + sr1) + (sr2 + sr3);
    }
    __syncthreads();

    // phase 3: 32*64 = 2048 outputs for this d-half
    __nv_bfloat16* bwh = g_bwh + (size_t)bh * HD * 128;
    __nv_bfloat16* bwl = g_bwl + (size_t)bh * HD * 128;
    for (int it = t; it < 32 * HD; it += 256) {
        int d = it >> 6, o = it & 63;        // d local 0..31
        float ae = 0.f, ar = 0.f;
#pragma unroll
        for (int e = 0; e < LR; e++) {
            ae += web[d * LR + e] * cws[o * (2 * LR) + e];
            ar += wrb[d * LR + e] * cws[o * (2 * LR) + LR + e];
        }
        int dg = dbase + d;
        __nv_bfloat16 ha = __float2bfloat16(ae);
        __nv_bfloat16 hr = __float2bfloat16(ar);
        bwh[o * 128 + dg]      = ha;
        bwh[o * 128 + 64 + dg] = hr;
        bwl[o * 128 + dg]      = __float2bfloat16(ae - __bfloat162float(ha));
        bwl[o * 128 + 64 + dg] = __float2bfloat16(ar - __bfloat162float(hr));
    }
}

// ---------------------------------------------------------------------------
// score via HMMA: per bh, attn_tile[256,64] = QK[256,128] @ BW[64,128]^T + cw_b
// 3-term bf16 split; output written directly as bf16 hi/lo (feeds GEMM2).
// ---------------------------------------------------------------------------
#define SC_SMEM ((2 * 256 * LDT + 2 * 64 * LDT) * 2)

__global__ __launch_bounds__(256, 2) void score_mma_kernel(const float* __restrict__ cw_b)
{
    extern __shared__ __nv_bfloat16 ssm[];
    __nv_bfloat16* sAh = ssm;                      // 256*40
    __nv_bfloat16* sAl = ssm + 256 * LDT;
    __nv_bfloat16* sBh = ssm + 2 * 256 * LDT;      // 64*40
    __nv_bfloat16* sBl = ssm + 2 * 256 * LDT + 64 * LDT;

    const int t = threadIdx.x;
    const int lane = t & 31, wid = t >> 5;
    const int warpM = wid >> 1;
    const int warpN = wid & 1;
    const int tileM = blockIdx.x;      // 0..7 (256-token tiles)
    const int bh = blockIdx.y;
    const int b = bh >> 4, h = bh & 15;

    const __nv_bfloat16* Abh = g_qnh + ((size_t)bh * NN + tileM * 256) * 128;
    const __nv_bfloat16* Abl = g_qnl + ((size_t)bh * NN + tileM * 256) * 128;
    const __nv_bfloat16* Bbh = g_bwh + (size_t)bh * HD * 128;
    const __nv_bfloat16* Bbl = g_bwl + (size_t)bh * HD * 128;

    const uint32_t smb = smem_u32(ssm);
    const uint32_t offAl = 256 * LDT * 2;
    const uint32_t offBh = 2 * 256 * LDT * 2;
    const uint32_t offBl = offBh + 64 * LDT * 2;

    float acc[4][4][4];
#pragma unroll
    for (int m = 0; m < 4; m++)
#pragma unroll
        for (int n = 0; n < 4; n++)
#pragma unroll
            for (int j = 0; j < 4; j++) acc[m][n][j] = 0.f;

    const int a_row = warpM * 64 + (lane & 15);
    const int a_colh = (lane >> 4) << 3;
    const int b_row = warpN * 32 + ((lane >> 4) << 3) + (lane & 7);
    const int b_colh = ((lane >> 3) & 1) << 3;

    for (int ck = 0; ck < 4; ck++) {
        int kt = ck * 32;
        if (ck) __syncthreads();
#pragma unroll
        for (int j = 0; j < 4; j++) {
            int idx = t + j * 256;
            int row = idx >> 2, c = idx & 3;
            *(uint4*)(sAh + row * LDT + c * 8) = *(const uint4*)(Abh + (size_t)row * 128 + kt + c * 8);
            *(uint4*)(sAl + row * LDT + c * 8) = *(const uint4*)(Abl + (size_t)row * 128 + kt + c * 8);
        }
        {
            int row = t >> 2, c = t & 3;
            if (row < 64) {
                *(uint4*)(sBh + row * LDT + c * 8) = *(const uint4*)(Bbh + (size_t)row * 128 + kt + c * 8);
                *(uint4*)(sBl + row * LDT + c * 8) = *(const uint4*)(Bbl + (size_t)row * 128 + kt + c * 8);
            }
        }
        __syncthreads();

#pragma unroll
        for (int kk = 0; kk < 32; kk += 16) {
            uint32_t ahf[4][4], alf[4][4];
#pragma unroll
            for (int m = 0; m < 4; m++) {
                uint32_t off = ((a_row + m * 16) * LDT + kk + a_colh) * 2;
                ldm_x4(ahf[m], smb + off);
                ldm_x4(alf[m], smb + offAl + off);
            }
            uint32_t bhf[2][4], blf[2][4];
#pragma unroll
            for (int p = 0; p < 2; p++) {
                uint32_t off = ((b_row + p * 16) * LDT + kk + b_colh) * 2;
                ldm_x4(bhf[p], smb + offBh + off);
                ldm_x4(blf[p], smb + offBl + off);
            }
#pragma unroll
            for (int m = 0; m < 4; m++) {
#pragma unroll
                for (int n = 0; n < 4; n++) {
                    const uint32_t* b2h = &bhf[n >> 1][(n & 1) * 2];
                    const uint32_t* b2l = &blf[n >> 1][(n & 1) * 2];
                    mma_bf16(acc[m][n], ahf[m], b2h);
                    mma_bf16(acc[m][n], ahf[m], b2l);
                    mma_bf16(acc[m][n], alf[m], b2h);
                }
            }
        }
    }

    const int g = lane >> 2;
    const int cp = (lane & 3) * 2;
#pragma unroll
    for (int m = 0; m < 4; m++) {
        int n_tok = tileM * 256 + warpM * 64 + m * 16 + g;
#pragma unroll
        for (int n = 0; n < 4; n++) {
            int col = warpN * 32 + n * 8 + cp;
            float b0 = cw_b[col], b1 = cw_b[col + 1];
            size_t r0 = ((size_t)(b * NN + n_tok)) * CC + h * HD + col;
            size_t r1 = ((size_t)(b * NN + n_tok + 8)) * CC + h * HD + col;
            split_store2(acc[m][n][0] + b0, acc[m][n][1] + b1, g_ah + r0, g_al + r0);
            split_store2(acc[m][n][2] + b0, acc[m][n][3] + b1, g_ah + r1, g_al + r1);
        }
    }
}

// ---------------------------------------------------------------------------
extern "C" void kernel_launch(void* const* d_in, const int* in_sizes, int n_in,
                              void* d_out, int out_size)
{
    const float* x      = (const float*)d_in[0];
    const float* qk_w   = (const float*)d_in[1];
    const float* proj_w = (const float*)d_in[2];
    const float* proj_b = (const float*)d_in[3];
    const float* we     = (const float*)d_in[4];
    const float* wr     = (const float*)d_in[5];
    const float* cw_w   = (const float*)d_in[6];
    const float* cw_b   = (const float*)d_in[7];
    float* out = (float*)d_out;

    void *p_qk, *p_xh, *p_xl, *p_qkwh, *p_qkwl, *p_pwh, *p_pwl, *p_ah, *p_al;
    cudaGetSymbolAddress(&p_qk, g_qk);
    cudaGetSymbolAddress(&p_xh, g_xh);
    cudaGetSymbolAddress(&p_xl, g_xl);
    cudaGetSymbolAddress(&p_qkwh, g_qkwh);
    cudaGetSymbolAddress(&p_qkwl, g_qkwl);
    cudaGetSymbolAddress(&p_pwh, g_pwh);
    cudaGetSymbolAddress(&p_pwl, g_pwl);
    cudaGetSymbolAddress(&p_ah, g_ah);
    cudaGetSymbolAddress(&p_al, g_al);
    float* qk = (float*)p_qk;

    cudaFuncSetAttribute(gemm3h_kernel<false>, cudaFuncAttributeMaxDynamicSharedMemorySize, GEMM_SMEM);
    cudaFuncSetAttribute(gemm3h_kernel<true>,  cudaFuncAttributeMaxDynamicSharedMemorySize, GEMM_SMEM);
    cudaFuncSetAttribute(score_mma_kernel, cudaFuncAttributeMaxDynamicSharedMemorySize, SC_SMEM);
    cudaFuncSetAttribute(genw_kernel, cudaFuncAttributeMaxDynamicSharedMemorySize, GENW_SMEM);

    // 0) split x, qk_w, proj_w to bf16 hi/lo (one launch)
    split3_kernel<<<(N4_TOT + 255) / 256, 256>>>(x, qk_w, proj_w);

    // 1) qk = x @ qk_w^T  (HMMA, bf16 x3, cp.async, 2 CTAs/SM)
    gemm3h_kernel<false><<<dim3(2 * CC / 128, M_TOK / 128), 256, GEMM_SMEM>>>(
        (const __nv_bfloat16*)p_xh, (const __nv_bfloat16*)p_xl,
        (const __nv_bfloat16*)p_qkwh, (const __nv_bfloat16*)p_qkwl,
        nullptr, qk, M_TOK, 2 * CC, CC);

    // 2) normalize q/k -> bf16 hi/lo per-head layout
    l2norm2_kernel<<<(M_TOK * HH) / 8, 256>>>(qk);

    // 3) fold low-rank weights -> BW bf16 hi/lo (smem-staged, 128 CTAs)
    genw_kernel<<<dim3(BB * HH, 2), 256, GENW_SMEM>>>(x, we, wr, cw_w);

    // 4) attn = [q|k] @ BW^T + cw_b  (HMMA), output split bf16 hi/lo
    score_mma_kernel<<<dim3(NN / 256, BB * HH), 256, SC_SMEM>>>(cw_b);

    // 5) out = attn @ proj_w^T + proj_b  (HMMA, bf16 x3, cp.async, 2 CTAs/SM)
    gemm3h_kernel<true><<<dim3(CC / 128, M_TOK / 128), 256, GEMM_SMEM>>>(
        (const __nv_bfloat16*)p_ah, (const __nv_bfloat16*)p_al,
        (const __nv_bfloat16*)p_pwh, (const __nv_bfloat16*)p_pwl,
        proj_b, out, M_TOK, CC, CC);
}